// round 1
// baseline (speedup 1.0000x reference)
#include <cuda_runtime.h>
#include <math.h>
#include <stdint.h>

// Problem constants
#define BB 32
#define TT 128
#define DD 128
#define HH 8
#define HD 16
#define LL 4
#define VV 50257
#define BT (BB * TT)      // 4096
#define DFF (4 * DD)      // 512

// ---------------- scratch (device globals; no allocation) ----------------
__device__ float g_x[BT * DD];
__device__ float g_h[BT * DD];
__device__ float g_q[BT * DD];
__device__ float g_k[BT * DD];
__device__ float g_v[BT * DD];
__device__ float g_o[BT * DD];
__device__ float g_m[BT * DFF];
__device__ float g_wq[LL * DD * DD];
__device__ float g_wk[LL * DD * DD];
__device__ float g_wv[LL * DD * DD];
__device__ float g_nll[BT];

// ---------------- embedding ----------------
__global__ void embed_k(const int* __restrict__ idx,
                        const float* __restrict__ tok,
                        const float* __restrict__ pos) {
    int m = blockIdx.x;          // token row 0..4095
    int d = threadIdx.x;         // 0..127
    int t = m & (TT - 1);
    g_x[m * DD + d] = tok[(size_t)idx[m] * DD + d] + pos[t * DD + d];
}

// ---------------- repack qkv weights [L,H,D,HD] -> [L, D, H*HD] ----------------
__global__ void repack_k(const float* __restrict__ wq,
                         const float* __restrict__ wk,
                         const float* __restrict__ wv) {
    int o = blockIdx.x * blockDim.x + threadIdx.x;
    if (o >= LL * DD * DD) return;
    int l = o >> 14;
    int rem = o & 16383;
    int d = rem >> 7;
    int n = rem & 127;
    int h = n >> 4;
    int e = n & 15;
    int in = ((l * HH + h) * DD + d) * HD + e;
    g_wq[o] = wq[in];
    g_wk[o] = wk[in];
    g_wv[o] = wv[in];
}

// ---------------- layernorm (one block per row, 128 threads) ----------------
__global__ void ln_k(const float* __restrict__ in, float* __restrict__ out,
                     const float* __restrict__ gam, const float* __restrict__ bet) {
    __shared__ float red[4];
    int m = blockIdx.x, d = threadIdx.x;
    float x = in[m * DD + d];
    float s = x;
#pragma unroll
    for (int o = 16; o > 0; o >>= 1) s += __shfl_xor_sync(0xffffffffu, s, o);
    if ((d & 31) == 0) red[d >> 5] = s;
    __syncthreads();
    float mean = (red[0] + red[1] + red[2] + red[3]) * (1.0f / DD);
    __syncthreads();
    float c = x - mean;
    float cs = c * c;
#pragma unroll
    for (int o = 16; o > 0; o >>= 1) cs += __shfl_xor_sync(0xffffffffu, cs, o);
    if ((d & 31) == 0) red[d >> 5] = cs;
    __syncthreads();
    float var = (red[0] + red[1] + red[2] + red[3]) * (1.0f / DD);
    out[m * DD + d] = c * rsqrtf(var + 1e-5f) * gam[d] + bet[d];
}

// ---------------- attention: one block per (b,h), thread = query row ----------------
__global__ void attn_k() {
    int b = blockIdx.x / HH;
    int h = blockIdx.x % HH;
    int t = threadIdx.x;  // 0..127
    __shared__ float ks[TT][HD];
    __shared__ float vs[TT][HD];
#pragma unroll
    for (int e = 0; e < HD; e++) {
        ks[t][e] = g_k[(b * TT + t) * DD + h * HD + e];
        vs[t][e] = g_v[(b * TT + t) * DD + h * HD + e];
    }
    __syncthreads();
    float q[HD];
#pragma unroll
    for (int e = 0; e < HD; e++) q[e] = g_q[(b * TT + t) * DD + h * HD + e];

    const float scale = 0.08838834764831845f;  // 1/sqrt(128) -- reference uses D^-0.5
    float mrun = -1e30f, lrun = 0.0f;
    float acc[HD];
#pragma unroll
    for (int e = 0; e < HD; e++) acc[e] = 0.0f;

    for (int s = 0; s <= t; s++) {
        float d = 0.0f;
#pragma unroll
        for (int e = 0; e < HD; e++) d += q[e] * ks[s][e];
        d *= scale;
        float mn = fmaxf(mrun, d);
        float corr = __expf(mrun - mn);
        float p = __expf(d - mn);
        lrun = lrun * corr + p;
#pragma unroll
        for (int e = 0; e < HD; e++) acc[e] = acc[e] * corr + p * vs[s][e];
        mrun = mn;
    }
    float inv = 1.0f / lrun;
#pragma unroll
    for (int e = 0; e < HD; e++)
        g_o[(b * TT + t) * DD + h * HD + e] = acc[e] * inv;
}

// ---------------- generic tiled SGEMM: C[M,N] = A[M,K] @ B[K,N] (+bias/relu/residual) ----------------
// BM=BN=128, BK=16, 256 threads, 8x8 per thread.
// flags: 1=bias, 2=relu, 4=residual
template <bool VECB>
__global__ void __launch_bounds__(256) gemm_k(
    const float* __restrict__ A, const float* __restrict__ Bm,
    const float* __restrict__ bias, const float* __restrict__ Rres,
    float* __restrict__ C, int M, int N, int K, int flags) {
    __shared__ float As[16][128];
    __shared__ float Bs[16][128];
    int bm0 = blockIdx.y * 128;
    int bn0 = blockIdx.x * 128;
    int tid = threadIdx.x;
    int ty = tid >> 4, tx = tid & 15;

    float acc[8][8];
#pragma unroll
    for (int i = 0; i < 8; i++)
#pragma unroll
        for (int j = 0; j < 8; j++) acc[i][j] = 0.0f;

    int ar = tid >> 2;            // 0..63
    int ac = (tid & 3) << 2;      // 0,4,8,12
    int br = tid >> 5;            // 0..7
    int bc = (tid & 31) << 2;     // 0..124

    for (int k0 = 0; k0 < K; k0 += 16) {
        // A tile (128x16), stored transposed As[k][m]
        float4 a0 = *(const float4*)&A[(size_t)(bm0 + ar) * K + k0 + ac];
        float4 a1 = *(const float4*)&A[(size_t)(bm0 + ar + 64) * K + k0 + ac];
        As[ac + 0][ar] = a0.x; As[ac + 1][ar] = a0.y;
        As[ac + 2][ar] = a0.z; As[ac + 3][ar] = a0.w;
        As[ac + 0][ar + 64] = a1.x; As[ac + 1][ar + 64] = a1.y;
        As[ac + 2][ar + 64] = a1.z; As[ac + 3][ar + 64] = a1.w;
        // B tile (16x128)
        if (VECB) {
            float4 b0 = *(const float4*)&Bm[(size_t)(k0 + br) * N + bn0 + bc];
            float4 b1 = *(const float4*)&Bm[(size_t)(k0 + br + 8) * N + bn0 + bc];
            Bs[br][bc + 0] = b0.x; Bs[br][bc + 1] = b0.y;
            Bs[br][bc + 2] = b0.z; Bs[br][bc + 3] = b0.w;
            Bs[br + 8][bc + 0] = b1.x; Bs[br + 8][bc + 1] = b1.y;
            Bs[br + 8][bc + 2] = b1.z; Bs[br + 8][bc + 3] = b1.w;
        } else {
#pragma unroll
            for (int i = 0; i < 4; i++) {
                int col = bn0 + bc + i;
                Bs[br][bc + i] = (col < N) ? Bm[(size_t)(k0 + br) * N + col] : 0.0f;
                Bs[br + 8][bc + i] = (col < N) ? Bm[(size_t)(k0 + br + 8) * N + col] : 0.0f;
            }
        }
        __syncthreads();
#pragma unroll
        for (int kk = 0; kk < 16; kk++) {
            float a[8], bf[8];
#pragma unroll
            for (int i = 0; i < 8; i++) a[i] = As[kk][ty * 8 + i];
#pragma unroll
            for (int j = 0; j < 8; j++) bf[j] = Bs[kk][tx * 8 + j];
#pragma unroll
            for (int i = 0; i < 8; i++)
#pragma unroll
                for (int j = 0; j < 8; j++) acc[i][j] += a[i] * bf[j];
        }
        __syncthreads();
    }
    // epilogue
#pragma unroll
    for (int i = 0; i < 8; i++) {
        int row = bm0 + ty * 8 + i;
#pragma unroll
        for (int j = 0; j < 8; j++) {
            int col = bn0 + tx * 8 + j;
            if (col < N) {
                float v = acc[i][j];
                if (flags & 1) v += bias[col];
                if (flags & 2) v = fmaxf(v, 0.0f);
                if (flags & 4) v += Rres[(size_t)row * N + col];
                C[(size_t)row * N + col] = v;
            }
        }
    }
}

// ---------------- per-row NLL: logsumexp(logits_row) - logits_row[target] ----------------
__global__ void nll_k(const float* __restrict__ logits, const int* __restrict__ tgt) {
    int r = blockIdx.x;
    int tid = threadIdx.x;  // 256
    const float* row = logits + (size_t)r * VV;
    float m = -1e30f, s = 0.0f;
    for (int c = tid; c < VV; c += 256) {
        float x = row[c];
        if (x > m) {
            s = s * __expf(m - x) + 1.0f;
            m = x;
        } else {
            s += __expf(x - m);
        }
    }
    __shared__ float sm[256], ss[256];
    sm[tid] = m; ss[tid] = s;
    __syncthreads();
    for (int o = 128; o > 0; o >>= 1) {
        if (tid < o) {
            float m2 = sm[tid + o], s2 = ss[tid + o];
            float mm = fmaxf(sm[tid], m2);
            ss[tid] = ss[tid] * __expf(sm[tid] - mm) + s2 * __expf(m2 - mm);
            sm[tid] = mm;
        }
        __syncthreads();
    }
    if (tid == 0) g_nll[r] = sm[0] + logf(ss[0]) - row[tgt[r]];
}

__global__ void loss_k(float* __restrict__ out) {
    __shared__ float accs[256];
    float s = 0.0f;
    for (int i = threadIdx.x; i < BT; i += 256) s += g_nll[i];
    accs[threadIdx.x] = s;
    __syncthreads();
    for (int o = 128; o > 0; o >>= 1) {
        if (threadIdx.x < o) accs[threadIdx.x] += accs[threadIdx.x + o];
        __syncthreads();
    }
    if (threadIdx.x == 0) out[0] = accs[0] * (1.0f / BT);
}

// ---------------- host launcher ----------------
static void launch_gemm(const float* A, const float* B, const float* bias,
                        const float* res, float* C, int M, int N, int K, int flags) {
    dim3 grid((N + 127) / 128, (M + 127) / 128);
    if (N % 128 == 0)
        gemm_k<true><<<grid, 256>>>(A, B, bias, res, C, M, N, K, flags);
    else
        gemm_k<false><<<grid, 256>>>(A, B, bias, res, C, M, N, K, flags);
}

extern "C" void kernel_launch(void* const* d_in, const int* in_sizes, int n_in,
                              void* d_out, int out_size) {
    const int* idx       = (const int*)d_in[0];
    const int* targets   = (const int*)d_in[1];
    const float* tok_emb = (const float*)d_in[2];
    const float* pos_emb = (const float*)d_in[3];
    const float* wq      = (const float*)d_in[4];
    const float* wk      = (const float*)d_in[5];
    const float* wv      = (const float*)d_in[6];
    const float* wproj   = (const float*)d_in[7];
    const float* bproj   = (const float*)d_in[8];
    const float* w1      = (const float*)d_in[9];
    const float* b1      = (const float*)d_in[10];
    const float* w2      = (const float*)d_in[11];
    const float* b2      = (const float*)d_in[12];
    const float* ln1_g   = (const float*)d_in[13];
    const float* ln1_b   = (const float*)d_in[14];
    const float* ln2_g   = (const float*)d_in[15];
    const float* ln2_b   = (const float*)d_in[16];
    const float* lnf_g   = (const float*)d_in[17];
    const float* lnf_b   = (const float*)d_in[18];
    const float* lm_w    = (const float*)d_in[19];
    const float* lm_b    = (const float*)d_in[20];
    float* out = (float*)d_out;

    float *px, *ph, *pq, *pk, *pv, *po, *pm;
    float *pwq, *pwk, *pwv;
    cudaGetSymbolAddress((void**)&px, g_x);
    cudaGetSymbolAddress((void**)&ph, g_h);
    cudaGetSymbolAddress((void**)&pq, g_q);
    cudaGetSymbolAddress((void**)&pk, g_k);
    cudaGetSymbolAddress((void**)&pv, g_v);
    cudaGetSymbolAddress((void**)&po, g_o);
    cudaGetSymbolAddress((void**)&pm, g_m);
    cudaGetSymbolAddress((void**)&pwq, g_wq);
    cudaGetSymbolAddress((void**)&pwk, g_wk);
    cudaGetSymbolAddress((void**)&pwv, g_wv);

    // Embedding + weight repack
    embed_k<<<BT, DD>>>(idx, tok_emb, pos_emb);
    repack_k<<<(LL * DD * DD + 255) / 256, 256>>>(wq, wk, wv);

    for (int l = 0; l < LL; l++) {
        // LN1
        ln_k<<<BT, DD>>>(px, ph, ln1_g + l * DD, ln1_b + l * DD);
        // QKV
        launch_gemm(ph, pwq + l * DD * DD, nullptr, nullptr, pq, BT, DD, DD, 0);
        launch_gemm(ph, pwk + l * DD * DD, nullptr, nullptr, pk, BT, DD, DD, 0);
        launch_gemm(ph, pwv + l * DD * DD, nullptr, nullptr, pv, BT, DD, DD, 0);
        // attention
        attn_k<<<BB * HH, TT>>>();
        // proj + residual
        launch_gemm(po, wproj + l * DD * DD, bproj + l * DD, px, px, BT, DD, DD, 1 | 4);
        // LN2
        ln_k<<<BT, DD>>>(px, ph, ln2_g + l * DD, ln2_b + l * DD);
        // MLP
        launch_gemm(ph, w1 + l * DD * DFF, b1 + l * DFF, nullptr, pm, BT, DFF, DD, 1 | 2);
        launch_gemm(pm, w2 + l * DFF * DD, b2 + l * DD, px, px, BT, DD, DFF, 1 | 4);
    }

    // final LN
    ln_k<<<BT, DD>>>(px, ph, lnf_g, lnf_b);
    // logits = h @ lm_w + lm_b  -> d_out
    launch_gemm(ph, lm_w, lm_b, nullptr, out, BT, VV, DD, 1);
    // loss
    nll_k<<<BT, 256>>>(out, targets);
    if (out_size > BT * VV) {
        loss_k<<<1, 256>>>(out + (size_t)BT * VV);
    }
}

// round 3
// speedup vs baseline: 1.5130x; 1.5130x over previous
#include <cuda_runtime.h>
#include <math.h>
#include <stdint.h>

#define BB 32
#define TT 128
#define DD 128
#define HH 8
#define HD 16
#define LL 4
#define VV 50257
#define BT (BB * TT)       // 4096
#define DFF (4 * DD)       // 512
#define NCB ((VV + 127) / 128)  // 393 col-blocks for LM head

// ---------------- scratch ----------------
__device__ float g_x[BT * DD];
__device__ float g_h[BT * DD];
__device__ float g_qkv[BT * 384];
__device__ float g_o[BT * DD];
__device__ float g_m[BT * DFF];
__device__ float g_wqkv[LL * DD * 384];
__device__ float g_part[BT * NCB];
__device__ float g_nll[BT];

// ---------------- embedding ----------------
__global__ void embed_k(const int* __restrict__ idx,
                        const float* __restrict__ tok,
                        const float* __restrict__ pos) {
    int m = blockIdx.x;
    int d = threadIdx.x;
    int t = m & (TT - 1);
    g_x[m * DD + d] = tok[(size_t)idx[m] * DD + d] + pos[t * DD + d];
}

// ---------------- repack qkv weights [L,H,D,HD] -> [L, D, 384] ----------------
__global__ void repack_k(const float* __restrict__ wq,
                         const float* __restrict__ wk,
                         const float* __restrict__ wv) {
    int o = blockIdx.x * blockDim.x + threadIdx.x;
    if (o >= LL * DD * DD) return;
    int l = o >> 14;
    int rem = o & 16383;
    int d = rem >> 7;
    int n = rem & 127;
    int h = n >> 4;
    int e = n & 15;
    int in = ((l * HH + h) * DD + d) * HD + e;
    float* W = g_wqkv + (size_t)l * DD * 384 + d * 384;
    W[n]       = wq[in];
    W[128 + n] = wk[in];
    W[256 + n] = wv[in];
}

// ---------------- layernorm ----------------
__global__ void ln_k(const float* __restrict__ in, float* __restrict__ out,
                     const float* __restrict__ gam, const float* __restrict__ bet) {
    __shared__ float red[4];
    int m = blockIdx.x, d = threadIdx.x;
    float x = in[m * DD + d];
    float s = x;
#pragma unroll
    for (int o = 16; o > 0; o >>= 1) s += __shfl_xor_sync(0xffffffffu, s, o);
    if ((d & 31) == 0) red[d >> 5] = s;
    __syncthreads();
    float mean = (red[0] + red[1] + red[2] + red[3]) * (1.0f / DD);
    __syncthreads();
    float c = x - mean;
    float cs = c * c;
#pragma unroll
    for (int o = 16; o > 0; o >>= 1) cs += __shfl_xor_sync(0xffffffffu, cs, o);
    if ((d & 31) == 0) red[d >> 5] = cs;
    __syncthreads();
    float var = (red[0] + red[1] + red[2] + red[3]) * (1.0f / DD);
    out[m * DD + d] = c * rsqrtf(var + 1e-5f) * gam[d] + bet[d];
}

// ---------------- attention (qkv packed, pitch 384) ----------------
__global__ void attn_k() {
    int b = blockIdx.x / HH;
    int h = blockIdx.x % HH;
    int t = threadIdx.x;
    __shared__ float ks[TT][HD];
    __shared__ float vs[TT][HD];
    const float* rowp = g_qkv + (size_t)(b * TT + t) * 384 + h * HD;
#pragma unroll
    for (int e = 0; e < HD; e++) {
        ks[t][e] = rowp[128 + e];
        vs[t][e] = rowp[256 + e];
    }
    __syncthreads();
    float q[HD];
#pragma unroll
    for (int e = 0; e < HD; e++) q[e] = rowp[e];

    const float scale = 0.08838834764831845f;  // 1/sqrt(128)
    float mrun = -1e30f, lrun = 0.0f;
    float acc[HD];
#pragma unroll
    for (int e = 0; e < HD; e++) acc[e] = 0.0f;
    for (int s = 0; s <= t; s++) {
        float d = 0.0f;
#pragma unroll
        for (int e = 0; e < HD; e++) d += q[e] * ks[s][e];
        d *= scale;
        float mn = fmaxf(mrun, d);
        float corr = __expf(mrun - mn);
        float p = __expf(d - mn);
        lrun = lrun * corr + p;
#pragma unroll
        for (int e = 0; e < HD; e++) acc[e] = acc[e] * corr + p * vs[s][e];
        mrun = mn;
    }
    float inv = 1.0f / lrun;
#pragma unroll
    for (int e = 0; e < HD; e++)
        g_o[(size_t)(b * TT + t) * DD + h * HD + e] = acc[e] * inv;
}

// ---------------- body GEMM: 64x64 tiles, 128 threads, 8x4 micro ----------------
// flags: 1=bias, 2=relu, 4=residual. Requires N % 64 == 0, M % 64 == 0, K % 16 == 0.
__global__ void __launch_bounds__(128) gemm64_k(
    const float* __restrict__ A, const float* __restrict__ Bm,
    const float* __restrict__ bias, const float* __restrict__ Rres,
    float* __restrict__ C, int M, int N, int K, int flags) {
    __shared__ float As[16][64];
    __shared__ float Bs[16][64];
    int bm0 = blockIdx.y * 64;
    int bn0 = blockIdx.x * 64;
    int tid = threadIdx.x;
    int ty = tid >> 4;      // 0..7  (8 row-groups of 8)
    int tx = tid & 15;      // 0..15 (16 col-groups of 4)

    float acc[8][4];
#pragma unroll
    for (int i = 0; i < 8; i++)
#pragma unroll
        for (int j = 0; j < 4; j++) acc[i][j] = 0.0f;

    int ar = tid >> 1;            // 0..63
    int ac = (tid & 1) * 8;       // 0 or 8
    int br = tid >> 3;            // 0..15
    int bc = (tid & 7) * 8;       // 0..56

    for (int k0 = 0; k0 < K; k0 += 16) {
        float4 a0 = *(const float4*)&A[(size_t)(bm0 + ar) * K + k0 + ac];
        float4 a1 = *(const float4*)&A[(size_t)(bm0 + ar) * K + k0 + ac + 4];
        As[ac + 0][ar] = a0.x; As[ac + 1][ar] = a0.y;
        As[ac + 2][ar] = a0.z; As[ac + 3][ar] = a0.w;
        As[ac + 4][ar] = a1.x; As[ac + 5][ar] = a1.y;
        As[ac + 6][ar] = a1.z; As[ac + 7][ar] = a1.w;
        float4 b0 = *(const float4*)&Bm[(size_t)(k0 + br) * N + bn0 + bc];
        float4 b1 = *(const float4*)&Bm[(size_t)(k0 + br) * N + bn0 + bc + 4];
        *(float4*)&Bs[br][bc] = b0;
        *(float4*)&Bs[br][bc + 4] = b1;
        __syncthreads();
#pragma unroll
        for (int kk = 0; kk < 16; kk++) {
            float4 av0 = *(const float4*)&As[kk][ty * 8];
            float4 av1 = *(const float4*)&As[kk][ty * 8 + 4];
            float4 bv = *(const float4*)&Bs[kk][tx * 4];
            float a[8] = {av0.x, av0.y, av0.z, av0.w, av1.x, av1.y, av1.z, av1.w};
            float b[4] = {bv.x, bv.y, bv.z, bv.w};
#pragma unroll
            for (int i = 0; i < 8; i++)
#pragma unroll
                for (int j = 0; j < 4; j++) acc[i][j] += a[i] * b[j];
        }
        __syncthreads();
    }
    int colb = bn0 + tx * 4;
    float4 bb = make_float4(0.f, 0.f, 0.f, 0.f);
    if (flags & 1) bb = *(const float4*)&bias[colb];
#pragma unroll
    for (int i = 0; i < 8; i++) {
        int row = bm0 + ty * 8 + i;
        float4 v = make_float4(acc[i][0] + bb.x, acc[i][1] + bb.y,
                               acc[i][2] + bb.z, acc[i][3] + bb.w);
        if (flags & 2) {
            v.x = fmaxf(v.x, 0.f); v.y = fmaxf(v.y, 0.f);
            v.z = fmaxf(v.z, 0.f); v.w = fmaxf(v.w, 0.f);
        }
        if (flags & 4) {
            float4 r = *(const float4*)&Rres[(size_t)row * N + colb];
            v.x += r.x; v.y += r.y; v.z += r.z; v.w += r.w;
        }
        *(float4*)&C[(size_t)row * N + colb] = v;
    }
}

// ---------------- LM head: C[4096, V] = A[4096,128] @ B[128,V] + bias ----------------
// 128x128 tile, K=128 fixed, double-buffered, fused per-row sum(exp) partials.
__global__ void __launch_bounds__(256, 2) lmhead_k(
    const float* __restrict__ A, const float* __restrict__ Bm,
    const float* __restrict__ bias, float* __restrict__ C) {
    __shared__ float As[2][16][128];
    __shared__ float Bs[2][16][128];
    int bm0 = blockIdx.x * 128;
    int bn0 = blockIdx.y * 128;
    int tid = threadIdx.x;
    int ty = tid >> 4;   // 0..15
    int tx = tid & 15;   // 0..15

    int ar = tid >> 1;        // 0..127
    int ac = (tid & 1) * 8;   // 0 or 8

    float acc[8][8];
#pragma unroll
    for (int i = 0; i < 8; i++)
#pragma unroll
        for (int j = 0; j < 8; j++) acc[i][j] = 0.0f;

    float4 pa0, pa1;
    float pb[8];

    // prefetch tile 0
    pa0 = *(const float4*)&A[(size_t)(bm0 + ar) * DD + ac];
    pa1 = *(const float4*)&A[(size_t)(bm0 + ar) * DD + ac + 4];
#pragma unroll
    for (int i = 0; i < 8; i++) {
        int e = tid + i * 256;
        int row = e >> 7, col = e & 127;
        int gc = bn0 + col;
        pb[i] = (gc < VV) ? Bm[(size_t)row * VV + gc] : 0.0f;
    }
    // store tile 0
    As[0][ac + 0][ar] = pa0.x; As[0][ac + 1][ar] = pa0.y;
    As[0][ac + 2][ar] = pa0.z; As[0][ac + 3][ar] = pa0.w;
    As[0][ac + 4][ar] = pa1.x; As[0][ac + 5][ar] = pa1.y;
    As[0][ac + 6][ar] = pa1.z; As[0][ac + 7][ar] = pa1.w;
#pragma unroll
    for (int i = 0; i < 8; i++) {
        int e = tid + i * 256;
        Bs[0][e >> 7][e & 127] = pb[i];
    }
    __syncthreads();

#pragma unroll
    for (int t = 0; t < 8; t++) {
        int cur = t & 1;
        if (t < 7) {
            int k0 = (t + 1) * 16;
            pa0 = *(const float4*)&A[(size_t)(bm0 + ar) * DD + k0 + ac];
            pa1 = *(const float4*)&A[(size_t)(bm0 + ar) * DD + k0 + ac + 4];
#pragma unroll
            for (int i = 0; i < 8; i++) {
                int e = tid + i * 256;
                int row = e >> 7, col = e & 127;
                int gc = bn0 + col;
                pb[i] = (gc < VV) ? Bm[(size_t)(k0 + row) * VV + gc] : 0.0f;
            }
        }
#pragma unroll
        for (int kk = 0; kk < 16; kk++) {
            float4 av0 = *(const float4*)&As[cur][kk][ty * 8];
            float4 av1 = *(const float4*)&As[cur][kk][ty * 8 + 4];
            float4 bv0 = *(const float4*)&Bs[cur][kk][tx * 4];
            float4 bv1 = *(const float4*)&Bs[cur][kk][64 + tx * 4];
            float a[8] = {av0.x, av0.y, av0.z, av0.w, av1.x, av1.y, av1.z, av1.w};
            float b[8] = {bv0.x, bv0.y, bv0.z, bv0.w, bv1.x, bv1.y, bv1.z, bv1.w};
#pragma unroll
            for (int i = 0; i < 8; i++)
#pragma unroll
                for (int j = 0; j < 8; j++) acc[i][j] += a[i] * b[j];
        }
        if (t < 7) {
            int nxt = cur ^ 1;
            As[nxt][ac + 0][ar] = pa0.x; As[nxt][ac + 1][ar] = pa0.y;
            As[nxt][ac + 2][ar] = pa0.z; As[nxt][ac + 3][ar] = pa0.w;
            As[nxt][ac + 4][ar] = pa1.x; As[nxt][ac + 5][ar] = pa1.y;
            As[nxt][ac + 6][ar] = pa1.z; As[nxt][ac + 7][ar] = pa1.w;
#pragma unroll
            for (int i = 0; i < 8; i++) {
                int e = tid + i * 256;
                Bs[nxt][e >> 7][e & 127] = pb[i];
            }
            __syncthreads();
        }
    }

    // epilogue: store + fused sum(exp) partials (logits are O(1), no max needed)
    int cols[8];
    float bv[8];
#pragma unroll
    for (int j = 0; j < 8; j++) {
        cols[j] = bn0 + ((j < 4) ? (tx * 4 + j) : (60 + tx * 4 + j));
        bv[j] = (cols[j] < VV) ? bias[cols[j]] : 0.0f;
    }
#pragma unroll
    for (int i = 0; i < 8; i++) {
        int row = bm0 + ty * 8 + i;
        float s = 0.0f;
#pragma unroll
        for (int j = 0; j < 8; j++) {
            if (cols[j] < VV) {
                float v = acc[i][j] + bv[j];
                C[(size_t)row * VV + cols[j]] = v;
                s += __expf(v);
            }
        }
#pragma unroll
        for (int o = 1; o < 16; o <<= 1)
            s += __shfl_xor_sync(0xffffffffu, s, o);
        if (tx == 0) g_part[(size_t)row * NCB + blockIdx.y] = s;
    }
}

// ---------------- NLL from partials ----------------
__global__ void nllred_k(const float* __restrict__ logits, const int* __restrict__ tgt) {
    int r = blockIdx.x;
    int tid = threadIdx.x;  // 128
    float s = 0.0f;
    for (int c = tid; c < NCB; c += 128) s += g_part[(size_t)r * NCB + c];
    __shared__ float red[4];
#pragma unroll
    for (int o = 16; o > 0; o >>= 1) s += __shfl_xor_sync(0xffffffffu, s, o);
    if ((tid & 31) == 0) red[tid >> 5] = s;
    __syncthreads();
    if (tid == 0) {
        float tot = red[0] + red[1] + red[2] + red[3];
        g_nll[r] = logf(tot) - logits[(size_t)r * VV + tgt[r]];
    }
}

__global__ void loss_k(float* __restrict__ out) {
    __shared__ float accs[256];
    float s = 0.0f;
    for (int i = threadIdx.x; i < BT; i += 256) s += g_nll[i];
    accs[threadIdx.x] = s;
    __syncthreads();
    for (int o = 128; o > 0; o >>= 1) {
        if (threadIdx.x < o) accs[threadIdx.x] += accs[threadIdx.x + o];
        __syncthreads();
    }
    if (threadIdx.x == 0) out[0] = accs[0] * (1.0f / BT);
}

// ---------------- host launcher ----------------
static void launch_gemm64(const float* A, const float* B, const float* bias,
                          const float* res, float* C, int M, int N, int K, int flags) {
    dim3 grid(N / 64, M / 64);
    gemm64_k<<<grid, 128>>>(A, B, bias, res, C, M, N, K, flags);
}

extern "C" void kernel_launch(void* const* d_in, const int* in_sizes, int n_in,
                              void* d_out, int out_size) {
    const int* idx       = (const int*)d_in[0];
    const int* targets   = (const int*)d_in[1];
    const float* tok_emb = (const float*)d_in[2];
    const float* pos_emb = (const float*)d_in[3];
    const float* wq      = (const float*)d_in[4];
    const float* wk      = (const float*)d_in[5];
    const float* wv      = (const float*)d_in[6];
    const float* wproj   = (const float*)d_in[7];
    const float* bproj   = (const float*)d_in[8];
    const float* w1      = (const float*)d_in[9];
    const float* b1      = (const float*)d_in[10];
    const float* w2      = (const float*)d_in[11];
    const float* b2      = (const float*)d_in[12];
    const float* ln1_g   = (const float*)d_in[13];
    const float* ln1_b   = (const float*)d_in[14];
    const float* ln2_g   = (const float*)d_in[15];
    const float* ln2_b   = (const float*)d_in[16];
    const float* lnf_g   = (const float*)d_in[17];
    const float* lnf_b   = (const float*)d_in[18];
    const float* lm_w    = (const float*)d_in[19];
    const float* lm_b    = (const float*)d_in[20];
    float* out = (float*)d_out;

    float *px, *ph, *pqkv, *po, *pm, *pwqkv;
    cudaGetSymbolAddress((void**)&px, g_x);
    cudaGetSymbolAddress((void**)&ph, g_h);
    cudaGetSymbolAddress((void**)&pqkv, g_qkv);
    cudaGetSymbolAddress((void**)&po, g_o);
    cudaGetSymbolAddress((void**)&pm, g_m);
    cudaGetSymbolAddress((void**)&pwqkv, g_wqkv);

    embed_k<<<BT, DD>>>(idx, tok_emb, pos_emb);
    repack_k<<<(LL * DD * DD + 255) / 256, 256>>>(wq, wk, wv);

    for (int l = 0; l < LL; l++) {
        ln_k<<<BT, DD>>>(px, ph, ln1_g + l * DD, ln1_b + l * DD);
        launch_gemm64(ph, pwqkv + (size_t)l * DD * 384, nullptr, nullptr,
                      pqkv, BT, 384, DD, 0);
        attn_k<<<BB * HH, TT>>>();
        launch_gemm64(po, wproj + (size_t)l * DD * DD, bproj + l * DD, px, px,
                      BT, DD, DD, 1 | 4);
        ln_k<<<BT, DD>>>(px, ph, ln2_g + l * DD, ln2_b + l * DD);
        launch_gemm64(ph, w1 + (size_t)l * DD * DFF, b1 + l * DFF, nullptr,
                      pm, BT, DFF, DD, 1 | 2);
        launch_gemm64(pm, w2 + (size_t)l * DFF * DD, b2 + l * DD, px, px,
                      BT, DD, DFF, 1 | 4);
    }

    ln_k<<<BT, DD>>>(px, ph, lnf_g, lnf_b);

    dim3 lgrid(BT / 128, NCB);
    lmhead_k<<<lgrid, 256>>>(ph, lm_w, lm_b, out);

    nllred_k<<<BT, 128>>>(out, targets);
    if (out_size > BT * VV) {
        loss_k<<<1, 256>>>(out + (size_t)BT * VV);
    }
}

// round 6
// speedup vs baseline: 2.4093x; 1.5924x over previous
#include <cuda_runtime.h>
#include <cuda_bf16.h>
#include <math.h>
#include <stdint.h>

#define BB 32
#define TT 128
#define DD 128
#define HH 8
#define HD 16
#define LL 4
#define VV 50257
#define BT (BB * TT)       // 4096
#define DFF (4 * DD)       // 512
#define NBLK 394                 // ceil(VV / 128) col-blocks for LM head
#define NPART (NBLK * 2)         // 788 partial-sum slots per row (2 warp-halves)
#define NPAD (NBLK * 128)        // 50432

// ---------------- scratch ----------------
__device__ float g_x[BT * DD];
__device__ float g_h[BT * DD];
__device__ float g_qkv[BT * 384];
__device__ float g_o[BT * DD];
__device__ float g_m[BT * DFF];
__device__ float g_wqkv[LL * DD * 384];
__device__ float g_part[(size_t)BT * NPART];
__device__ float g_nll[BT];
__device__ __nv_bfloat16 g_ahi[BT * DD];
__device__ __nv_bfloat16 g_alo[BT * DD];
__device__ __nv_bfloat16 g_bhi[(size_t)NPAD * DD];
__device__ __nv_bfloat16 g_blo[(size_t)NPAD * DD];

// ---------------- embedding ----------------
__global__ void embed_k(const int* __restrict__ idx,
                        const float* __restrict__ tok,
                        const float* __restrict__ pos) {
    int m = blockIdx.x;
    int d = threadIdx.x;
    int t = m & (TT - 1);
    g_x[m * DD + d] = tok[(size_t)idx[m] * DD + d] + pos[t * DD + d];
}

// ---------------- repack qkv weights [L,H,D,HD] -> [L, D, 384] ----------------
__global__ void repack_k(const float* __restrict__ wq,
                         const float* __restrict__ wk,
                         const float* __restrict__ wv) {
    int o = blockIdx.x * blockDim.x + threadIdx.x;
    if (o >= LL * DD * DD) return;
    int l = o >> 14;
    int rem = o & 16383;
    int d = rem >> 7;
    int n = rem & 127;
    int h = n >> 4;
    int e = n & 15;
    int in = ((l * HH + h) * DD + d) * HD + e;
    float* W = g_wqkv + (size_t)l * DD * 384 + d * 384;
    W[n]       = wq[in];
    W[128 + n] = wk[in];
    W[256 + n] = wv[in];
}

// ---------------- layernorm ----------------
__global__ void ln_k(const float* __restrict__ in, float* __restrict__ out,
                     const float* __restrict__ gam, const float* __restrict__ bet) {
    __shared__ float red[4];
    int m = blockIdx.x, d = threadIdx.x;
    float x = in[m * DD + d];
    float s = x;
#pragma unroll
    for (int o = 16; o > 0; o >>= 1) s += __shfl_xor_sync(0xffffffffu, s, o);
    if ((d & 31) == 0) red[d >> 5] = s;
    __syncthreads();
    float mean = (red[0] + red[1] + red[2] + red[3]) * (1.0f / DD);
    __syncthreads();
    float c = x - mean;
    float cs = c * c;
#pragma unroll
    for (int o = 16; o > 0; o >>= 1) cs += __shfl_xor_sync(0xffffffffu, cs, o);
    if ((d & 31) == 0) red[d >> 5] = cs;
    __syncthreads();
    float var = (red[0] + red[1] + red[2] + red[3]) * (1.0f / DD);
    out[m * DD + d] = c * rsqrtf(var + 1e-5f) * gam[d] + bet[d];
}

// ---------------- attention ----------------
__global__ void attn_k() {
    int b = blockIdx.x / HH;
    int h = blockIdx.x % HH;
    int t = threadIdx.x;
    __shared__ float ks[TT][HD];
    __shared__ float vs[TT][HD];
    const float* rowp = g_qkv + (size_t)(b * TT + t) * 384 + h * HD;
#pragma unroll
    for (int e = 0; e < HD; e++) {
        ks[t][e] = rowp[128 + e];
        vs[t][e] = rowp[256 + e];
    }
    __syncthreads();
    float q[HD];
#pragma unroll
    for (int e = 0; e < HD; e++) q[e] = rowp[e];

    const float scale = 0.08838834764831845f;  // 1/sqrt(128)
    float mrun = -1e30f, lrun = 0.0f;
    float acc[HD];
#pragma unroll
    for (int e = 0; e < HD; e++) acc[e] = 0.0f;
    for (int s = 0; s <= t; s++) {
        float d = 0.0f;
#pragma unroll
        for (int e = 0; e < HD; e++) d += q[e] * ks[s][e];
        d *= scale;
        float mn = fmaxf(mrun, d);
        float corr = __expf(mrun - mn);
        float p = __expf(d - mn);
        lrun = lrun * corr + p;
#pragma unroll
        for (int e = 0; e < HD; e++) acc[e] = acc[e] * corr + p * vs[s][e];
        mrun = mn;
    }
    float inv = 1.0f / lrun;
#pragma unroll
    for (int e = 0; e < HD; e++)
        g_o[(size_t)(b * TT + t) * DD + h * HD + e] = acc[e] * inv;
}

// ---------------- body GEMM: 64x64 tiles, 128 threads ----------------
__global__ void __launch_bounds__(128) gemm64_k(
    const float* __restrict__ A, const float* __restrict__ Bm,
    const float* __restrict__ bias, const float* __restrict__ Rres,
    float* __restrict__ C, int M, int N, int K, int flags) {
    __shared__ float As[16][64];
    __shared__ float Bs[16][64];
    int bm0 = blockIdx.y * 64;
    int bn0 = blockIdx.x * 64;
    int tid = threadIdx.x;
    int ty = tid >> 4;
    int tx = tid & 15;

    float acc[8][4];
#pragma unroll
    for (int i = 0; i < 8; i++)
#pragma unroll
        for (int j = 0; j < 4; j++) acc[i][j] = 0.0f;

    int ar = tid >> 1;
    int ac = (tid & 1) * 8;
    int br = tid >> 3;
    int bc = (tid & 7) * 8;

    for (int k0 = 0; k0 < K; k0 += 16) {
        float4 a0 = *(const float4*)&A[(size_t)(bm0 + ar) * K + k0 + ac];
        float4 a1 = *(const float4*)&A[(size_t)(bm0 + ar) * K + k0 + ac + 4];
        As[ac + 0][ar] = a0.x; As[ac + 1][ar] = a0.y;
        As[ac + 2][ar] = a0.z; As[ac + 3][ar] = a0.w;
        As[ac + 4][ar] = a1.x; As[ac + 5][ar] = a1.y;
        As[ac + 6][ar] = a1.z; As[ac + 7][ar] = a1.w;
        float4 b0 = *(const float4*)&Bm[(size_t)(k0 + br) * N + bn0 + bc];
        float4 b1 = *(const float4*)&Bm[(size_t)(k0 + br) * N + bn0 + bc + 4];
        *(float4*)&Bs[br][bc] = b0;
        *(float4*)&Bs[br][bc + 4] = b1;
        __syncthreads();
#pragma unroll
        for (int kk = 0; kk < 16; kk++) {
            float4 av0 = *(const float4*)&As[kk][ty * 8];
            float4 av1 = *(const float4*)&As[kk][ty * 8 + 4];
            float4 bv = *(const float4*)&Bs[kk][tx * 4];
            float a[8] = {av0.x, av0.y, av0.z, av0.w, av1.x, av1.y, av1.z, av1.w};
            float b[4] = {bv.x, bv.y, bv.z, bv.w};
#pragma unroll
            for (int i = 0; i < 8; i++)
#pragma unroll
                for (int j = 0; j < 4; j++) acc[i][j] += a[i] * b[j];
        }
        __syncthreads();
    }
    int colb = bn0 + tx * 4;
    float4 bb = make_float4(0.f, 0.f, 0.f, 0.f);
    if (flags & 1) bb = *(const float4*)&bias[colb];
#pragma unroll
    for (int i = 0; i < 8; i++) {
        int row = bm0 + ty * 8 + i;
        float4 v = make_float4(acc[i][0] + bb.x, acc[i][1] + bb.y,
                               acc[i][2] + bb.z, acc[i][3] + bb.w);
        if (flags & 2) {
            v.x = fmaxf(v.x, 0.f); v.y = fmaxf(v.y, 0.f);
            v.z = fmaxf(v.z, 0.f); v.w = fmaxf(v.w, 0.f);
        }
        if (flags & 4) {
            float4 r = *(const float4*)&Rres[(size_t)row * N + colb];
            v.x += r.x; v.y += r.y; v.z += r.z; v.w += r.w;
        }
        *(float4*)&C[(size_t)row * N + colb] = v;
    }
}

// ---------------- fp32 -> (hi, lo) bf16 splits ----------------
__global__ void cvta_k(const float* __restrict__ h) {
    int i = blockIdx.x * 128 + threadIdx.x;
    float x = h[i];
    __nv_bfloat16 hi = __float2bfloat16(x);
    float lo = x - __bfloat162float(hi);
    g_ahi[i] = hi;
    g_alo[i] = __float2bfloat16(lo);
}

// lm_w [128, V] -> transposed padded [NPAD, 128] bf16 hi/lo (n-major)
__global__ void cvtb_k(const float* __restrict__ lm_w) {
    __shared__ float t[32][33];
    int n0 = blockIdx.x * 32, k0 = blockIdx.y * 32;
    int tx = threadIdx.x, ty = threadIdx.y;  // 32 x 8
    for (int i = ty; i < 32; i += 8) {
        int n = n0 + tx, k = k0 + i;
        t[i][tx] = (n < VV) ? lm_w[(size_t)k * VV + n] : 0.0f;
    }
    __syncthreads();
    for (int i = ty; i < 32; i += 8) {
        int n = n0 + i, k = k0 + tx;
        float x = t[tx][i];
        __nv_bfloat16 hi = __float2bfloat16(x);
        float lo = x - __bfloat162float(hi);
        g_bhi[(size_t)n * DD + k] = hi;
        g_blo[(size_t)n * DD + k] = __float2bfloat16(lo);
    }
}

// ---------------- mma.sync helper (baseline sm_80+ ISA, no 'a' features) ----------------
__device__ __forceinline__ void mma16816(float* c, const uint32_t* a,
                                         uint32_t b0, uint32_t b1) {
    asm volatile(
        "mma.sync.aligned.m16n8k16.row.col.f32.bf16.bf16.f32 "
        "{%0,%1,%2,%3}, {%4,%5,%6,%7}, {%8,%9}, {%0,%1,%2,%3};"
        : "+f"(c[0]), "+f"(c[1]), "+f"(c[2]), "+f"(c[3])
        : "r"(a[0]), "r"(a[1]), "r"(a[2]), "r"(a[3]), "r"(b0), "r"(b1));
}

// ---------------- HMMA LM head ----------------
// CTA: 128(M) x 128(N), K = 3x128 (split terms), 8 warps (4m x 2n), warp 32x64.
// SMEM: Ahi/Alo [128][136] bf16, Bhi/Blo [128][136] bf16 (n-major), bias[128].
#define PADH 136
#define ROWW (PADH / 2)           // 68 words per padded row
#define AH_OFF 0
#define AL_OFF (128 * PADH * 2)           // 34816
#define BH_OFF (2 * 128 * PADH * 2)       // 69632
#define BL_OFF (3 * 128 * PADH * 2)       // 104448
#define BIAS_OFF (4 * 128 * PADH * 2)     // 139264
#define LM_SMEM (BIAS_OFF + 128 * 4)      // 139776

__global__ void __launch_bounds__(256, 1) lmhead_k(
    const float* __restrict__ bias, float* __restrict__ C) {
    extern __shared__ __align__(16) char smem[];
    int tid = threadIdx.x;
    int wid = tid >> 5;
    int lane = tid & 31;
    int g = lane >> 2;
    int t4 = lane & 3;
    int bm0 = blockIdx.x * 128;
    int bn0 = blockIdx.y * 128;
    int wm = (wid >> 1) * 32;     // warp M offset in tile
    int wn = (wid & 1) * 64;      // warp N offset in tile

    // ---- load tiles (global row-major [*, 128] bf16 -> padded smem rows) ----
    {
        const uint4* gah = (const uint4*)g_ahi;
        const uint4* gal = (const uint4*)g_alo;
        const uint4* gbh = (const uint4*)g_bhi;
        const uint4* gbl = (const uint4*)g_blo;
#pragma unroll
        for (int i = tid; i < 2048; i += 256) {
            int row = i >> 4, cb = i & 15;
            size_t gi = (size_t)(bm0 + row) * 16 + cb;
            uint32_t so = (uint32_t)(row * PADH + cb * 8) * 2;
            *(uint4*)(smem + AH_OFF + so) = gah[gi];
            *(uint4*)(smem + AL_OFF + so) = gal[gi];
            size_t gj = (size_t)(bn0 + row) * 16 + cb;
            *(uint4*)(smem + BH_OFF + so) = gbh[gj];
            *(uint4*)(smem + BL_OFF + so) = gbl[gj];
        }
        float* bs = (float*)(smem + BIAS_OFF);
        if (tid < 128) {
            int c = bn0 + tid;
            bs[tid] = (c < VV) ? bias[c] : 0.0f;
        }
    }
    __syncthreads();

    const uint32_t* AH = (const uint32_t*)(smem + AH_OFF);
    const uint32_t* AL = (const uint32_t*)(smem + AL_OFF);
    const uint32_t* BH = (const uint32_t*)(smem + BH_OFF);
    const uint32_t* BL = (const uint32_t*)(smem + BL_OFF);

    float acc[2][8][4];
#pragma unroll
    for (int i = 0; i < 2; i++)
#pragma unroll
        for (int j = 0; j < 8; j++)
#pragma unroll
            for (int q = 0; q < 4; q++) acc[i][j][q] = 0.0f;

    // ---- mainloop: 3 split terms x 8 k-steps of 16, no syncs ----
#pragma unroll 1
    for (int seg = 0; seg < 3; seg++) {
        const uint32_t* A = (seg == 2) ? AL : AH;
        const uint32_t* B = (seg == 1) ? BL : BH;
#pragma unroll
        for (int ks = 0; ks < 8; ks++) {
            int k0h = ks * 8;  // word offset within padded row
            uint32_t a[2][4];
#pragma unroll
            for (int i = 0; i < 2; i++) {
                int base = (wm + i * 16 + g) * ROWW + k0h + t4;
                a[i][0] = A[base];
                a[i][1] = A[base + 8 * ROWW];
                a[i][2] = A[base + 4];
                a[i][3] = A[base + 8 * ROWW + 4];
            }
#pragma unroll
            for (int j = 0; j < 8; j++) {
                int nb = (wn + j * 8 + g) * ROWW + k0h + t4;
                uint32_t b0 = B[nb];
                uint32_t b1 = B[nb + 4];
                mma16816(acc[0][j], a[0], b0, b1);
                mma16816(acc[1][j], a[1], b0, b1);
            }
        }
    }

    // ---- epilogue: bias + store + per-row sum(exp) partials ----
    const float* bs = (const float*)(smem + BIAS_OFF);
#pragma unroll
    for (int i = 0; i < 2; i++) {
#pragma unroll
        for (int half = 0; half < 2; half++) {
            int gr = bm0 + wm + i * 16 + half * 8 + g;
            float s = 0.0f;
#pragma unroll
            for (int j = 0; j < 8; j++) {
                int lc = wn + j * 8 + 2 * t4;
                int col = bn0 + lc;
                float v0 = acc[i][j][half * 2 + 0] + bs[lc];
                float v1 = acc[i][j][half * 2 + 1] + bs[lc + 1];
                if (col < VV) {
                    C[(size_t)gr * VV + col] = v0;
                    s += __expf(v0);
                }
                if (col + 1 < VV) {
                    C[(size_t)gr * VV + col + 1] = v1;
                    s += __expf(v1);
                }
            }
            // reduce over the 4 lanes (t4) sharing this row
            s += __shfl_xor_sync(0xffffffffu, s, 1);
            s += __shfl_xor_sync(0xffffffffu, s, 2);
            if (t4 == 0)
                g_part[(size_t)gr * NPART + blockIdx.y * 2 + (wid & 1)] = s;
        }
    }
}

// ---------------- NLL from partials ----------------
__global__ void nllred_k(const float* __restrict__ logits, const int* __restrict__ tgt) {
    int r = blockIdx.x;
    int tid = threadIdx.x;  // 128
    float s = 0.0f;
    for (int c = tid; c < NPART; c += 128) s += g_part[(size_t)r * NPART + c];
    __shared__ float red[4];
#pragma unroll
    for (int o = 16; o > 0; o >>= 1) s += __shfl_xor_sync(0xffffffffu, s, o);
    if ((tid & 31) == 0) red[tid >> 5] = s;
    __syncthreads();
    if (tid == 0) {
        float tot = red[0] + red[1] + red[2] + red[3];
        g_nll[r] = logf(tot) - logits[(size_t)r * VV + tgt[r]];
    }
}

__global__ void loss_k(float* __restrict__ out) {
    __shared__ float accs[256];
    float s = 0.0f;
    for (int i = threadIdx.x; i < BT; i += 256) s += g_nll[i];
    accs[threadIdx.x] = s;
    __syncthreads();
    for (int o = 128; o > 0; o >>= 1) {
        if (threadIdx.x < o) accs[threadIdx.x] += accs[threadIdx.x + o];
        __syncthreads();
    }
    if (threadIdx.x == 0) out[0] = accs[0] * (1.0f / BT);
}

// ---------------- host launcher ----------------
static void launch_gemm64(const float* A, const float* B, const float* bias,
                          const float* res, float* C, int M, int N, int K, int flags) {
    dim3 grid(N / 64, M / 64);
    gemm64_k<<<grid, 128>>>(A, B, bias, res, C, M, N, K, flags);
}

extern "C" void kernel_launch(void* const* d_in, const int* in_sizes, int n_in,
                              void* d_out, int out_size) {
    const int* idx       = (const int*)d_in[0];
    const int* targets   = (const int*)d_in[1];
    const float* tok_emb = (const float*)d_in[2];
    const float* pos_emb = (const float*)d_in[3];
    const float* wq      = (const float*)d_in[4];
    const float* wk      = (const float*)d_in[5];
    const float* wv      = (const float*)d_in[6];
    const float* wproj   = (const float*)d_in[7];
    const float* bproj   = (const float*)d_in[8];
    const float* w1      = (const float*)d_in[9];
    const float* b1      = (const float*)d_in[10];
    const float* w2      = (const float*)d_in[11];
    const float* b2      = (const float*)d_in[12];
    const float* ln1_g   = (const float*)d_in[13];
    const float* ln1_b   = (const float*)d_in[14];
    const float* ln2_g   = (const float*)d_in[15];
    const float* ln2_b   = (const float*)d_in[16];
    const float* lnf_g   = (const float*)d_in[17];
    const float* lnf_b   = (const float*)d_in[18];
    const float* lm_w    = (const float*)d_in[19];
    const float* lm_b    = (const float*)d_in[20];
    float* out = (float*)d_out;

    float *px, *ph, *pqkv, *po, *pm, *pwqkv;
    cudaGetSymbolAddress((void**)&px, g_x);
    cudaGetSymbolAddress((void**)&ph, g_h);
    cudaGetSymbolAddress((void**)&pqkv, g_qkv);
    cudaGetSymbolAddress((void**)&po, g_o);
    cudaGetSymbolAddress((void**)&pm, g_m);
    cudaGetSymbolAddress((void**)&pwqkv, g_wqkv);

    cudaFuncSetAttribute(lmhead_k, cudaFuncAttributeMaxDynamicSharedMemorySize, LM_SMEM);

    embed_k<<<BT, DD>>>(idx, tok_emb, pos_emb);
    repack_k<<<(LL * DD * DD + 255) / 256, 256>>>(wq, wk, wv);
    // pack lm_w -> transposed bf16 hi/lo (independent of body)
    cvtb_k<<<dim3(NPAD / 32, 4), dim3(32, 8)>>>(lm_w);

    for (int l = 0; l < LL; l++) {
        ln_k<<<BT, DD>>>(px, ph, ln1_g + l * DD, ln1_b + l * DD);
        launch_gemm64(ph, pwqkv + (size_t)l * DD * 384, nullptr, nullptr,
                      pqkv, BT, 384, DD, 0);
        attn_k<<<BB * HH, TT>>>();
        launch_gemm64(po, wproj + (size_t)l * DD * DD, bproj + l * DD, px, px,
                      BT, DD, DD, 1 | 4);
        ln_k<<<BT, DD>>>(px, ph, ln2_g + l * DD, ln2_b + l * DD);
        launch_gemm64(ph, w1 + (size_t)l * DD * DFF, b1 + l * DFF, nullptr,
                      pm, BT, DFF, DD, 1 | 2);
        launch_gemm64(pm, w2 + (size_t)l * DFF * DD, b2 + l * DD, px, px,
                      BT, DD, DFF, 1 | 4);
    }

    ln_k<<<BT, DD>>>(px, ph, lnf_g, lnf_b);
    cvta_k<<<BT, DD>>>(ph);

    dim3 lgrid(BT / 128, NBLK);
    lmhead_k<<<lgrid, 256, LM_SMEM>>>(lm_b, out);

    nllred_k<<<BT, 128>>>(out, targets);
    if (out_size > BT * VV) {
        loss_k<<<1, 256>>>(out + (size_t)BT * VV);
    }
}

// round 9
// speedup vs baseline: 3.0834x; 1.2798x over previous
#include <cuda_runtime.h>
#include <cuda_bf16.h>
#include <cuda_fp16.h>
#include <math.h>
#include <stdint.h>

#define BB 32
#define TT 128
#define DD 128
#define HH 8
#define HD 16
#define LL 4
#define VV 50257
#define BT (BB * TT)       // 4096
#define DFF (4 * DD)       // 512
#define NBLK 393                 // ceil(VV / 128)
#define NPART (NBLK * 2)         // 786 partial slots per row
#define NPAD (NBLK * 128)        // 50304

// ---------------- scratch ----------------
__device__ float g_x[BT * DD];
__device__ float g_h[BT * DD];
__device__ float g_qkv[BT * 384];
__device__ float g_o[BT * DD];
__device__ float g_m[BT * DFF];
__device__ float g_wqkv[LL * DD * 384];
__device__ float g_part[(size_t)BT * NPART];
__device__ float g_nll[BT];
__device__ __half g_ah[BT * DD];
__device__ __half g_al[BT * DD];
__device__ __half g_bh[(size_t)NPAD * DD];

// ---------------- embedding ----------------
__global__ void embed_k(const int* __restrict__ idx,
                        const float* __restrict__ tok,
                        const float* __restrict__ pos) {
    int m = blockIdx.x;
    int d = threadIdx.x;
    int t = m & (TT - 1);
    g_x[m * DD + d] = tok[(size_t)idx[m] * DD + d] + pos[t * DD + d];
}

// ---------------- repack qkv weights [L,H,D,HD] -> [L, D, 384] ----------------
__global__ void repack_k(const float* __restrict__ wq,
                         const float* __restrict__ wk,
                         const float* __restrict__ wv) {
    int o = blockIdx.x * blockDim.x + threadIdx.x;
    if (o >= LL * DD * DD) return;
    int l = o >> 14;
    int rem = o & 16383;
    int d = rem >> 7;
    int n = rem & 127;
    int h = n >> 4;
    int e = n & 15;
    int in = ((l * HH + h) * DD + d) * HD + e;
    float* W = g_wqkv + (size_t)l * DD * 384 + d * 384;
    W[n]       = wq[in];
    W[128 + n] = wk[in];
    W[256 + n] = wv[in];
}

// ---------------- layernorm ----------------
__global__ void ln_k(const float* __restrict__ in, float* __restrict__ out,
                     const float* __restrict__ gam, const float* __restrict__ bet) {
    __shared__ float red[4];
    int m = blockIdx.x, d = threadIdx.x;
    float x = in[m * DD + d];
    float s = x;
#pragma unroll
    for (int o = 16; o > 0; o >>= 1) s += __shfl_xor_sync(0xffffffffu, s, o);
    if ((d & 31) == 0) red[d >> 5] = s;
    __syncthreads();
    float mean = (red[0] + red[1] + red[2] + red[3]) * (1.0f / DD);
    __syncthreads();
    float c = x - mean;
    float cs = c * c;
#pragma unroll
    for (int o = 16; o > 0; o >>= 1) cs += __shfl_xor_sync(0xffffffffu, cs, o);
    if ((d & 31) == 0) red[d >> 5] = cs;
    __syncthreads();
    float var = (red[0] + red[1] + red[2] + red[3]) * (1.0f / DD);
    out[m * DD + d] = c * rsqrtf(var + 1e-5f) * gam[d] + bet[d];
}

// ---------------- final LN fused with fp16 hi/lo split ----------------
__global__ void lnsplit_k(const float* __restrict__ in,
                          const float* __restrict__ gam, const float* __restrict__ bet) {
    __shared__ float red[4];
    int m = blockIdx.x, d = threadIdx.x;
    int i = m * DD + d;
    float x = in[i];
    float s = x;
#pragma unroll
    for (int o = 16; o > 0; o >>= 1) s += __shfl_xor_sync(0xffffffffu, s, o);
    if ((d & 31) == 0) red[d >> 5] = s;
    __syncthreads();
    float mean = (red[0] + red[1] + red[2] + red[3]) * (1.0f / DD);
    __syncthreads();
    float c = x - mean;
    float cs = c * c;
#pragma unroll
    for (int o = 16; o > 0; o >>= 1) cs += __shfl_xor_sync(0xffffffffu, cs, o);
    if ((d & 31) == 0) red[d >> 5] = cs;
    __syncthreads();
    float var = (red[0] + red[1] + red[2] + red[3]) * (1.0f / DD);
    float y = c * rsqrtf(var + 1e-5f) * gam[d] + bet[d];
    __half hi = __float2half(y);
    g_ah[i] = hi;
    g_al[i] = __float2half(y - __half2float(hi));
}

// ---------------- attention ----------------
__global__ void attn_k() {
    int b = blockIdx.x / HH;
    int h = blockIdx.x % HH;
    int t = threadIdx.x;
    __shared__ float ks[TT][HD];
    __shared__ float vs[TT][HD];
    const float* rowp = g_qkv + (size_t)(b * TT + t) * 384 + h * HD;
#pragma unroll
    for (int e = 0; e < HD; e++) {
        ks[t][e] = rowp[128 + e];
        vs[t][e] = rowp[256 + e];
    }
    __syncthreads();
    float q[HD];
#pragma unroll
    for (int e = 0; e < HD; e++) q[e] = rowp[e];

    const float scale = 0.08838834764831845f;  // 1/sqrt(128)
    float mrun = -1e30f, lrun = 0.0f;
    float acc[HD];
#pragma unroll
    for (int e = 0; e < HD; e++) acc[e] = 0.0f;
    for (int s = 0; s <= t; s++) {
        float d = 0.0f;
#pragma unroll
        for (int e = 0; e < HD; e++) d += q[e] * ks[s][e];
        d *= scale;
        float mn = fmaxf(mrun, d);
        float corr = __expf(mrun - mn);
        float p = __expf(d - mn);
        lrun = lrun * corr + p;
#pragma unroll
        for (int e = 0; e < HD; e++) acc[e] = acc[e] * corr + p * vs[s][e];
        mrun = mn;
    }
    float inv = 1.0f / lrun;
#pragma unroll
    for (int e = 0; e < HD; e++)
        g_o[(size_t)(b * TT + t) * DD + h * HD + e] = acc[e] * inv;
}

// ---------------- body GEMM: 64x64 tiles, 128 threads ----------------
__global__ void __launch_bounds__(128) gemm64_k(
    const float* __restrict__ A, const float* __restrict__ Bm,
    const float* __restrict__ bias, const float* __restrict__ Rres,
    float* __restrict__ C, int M, int N, int K, int flags) {
    __shared__ float As[16][64];
    __shared__ float Bs[16][64];
    int bm0 = blockIdx.y * 64;
    int bn0 = blockIdx.x * 64;
    int tid = threadIdx.x;
    int ty = tid >> 4;
    int tx = tid & 15;

    float acc[8][4];
#pragma unroll
    for (int i = 0; i < 8; i++)
#pragma unroll
        for (int j = 0; j < 4; j++) acc[i][j] = 0.0f;

    int ar = tid >> 1;
    int ac = (tid & 1) * 8;
    int br = tid >> 3;
    int bc = (tid & 7) * 8;

    for (int k0 = 0; k0 < K; k0 += 16) {
        float4 a0 = *(const float4*)&A[(size_t)(bm0 + ar) * K + k0 + ac];
        float4 a1 = *(const float4*)&A[(size_t)(bm0 + ar) * K + k0 + ac + 4];
        As[ac + 0][ar] = a0.x; As[ac + 1][ar] = a0.y;
        As[ac + 2][ar] = a0.z; As[ac + 3][ar] = a0.w;
        As[ac + 4][ar] = a1.x; As[ac + 5][ar] = a1.y;
        As[ac + 6][ar] = a1.z; As[ac + 7][ar] = a1.w;
        float4 b0 = *(const float4*)&Bm[(size_t)(k0 + br) * N + bn0 + bc];
        float4 b1 = *(const float4*)&Bm[(size_t)(k0 + br) * N + bn0 + bc + 4];
        *(float4*)&Bs[br][bc] = b0;
        *(float4*)&Bs[br][bc + 4] = b1;
        __syncthreads();
#pragma unroll
        for (int kk = 0; kk < 16; kk++) {
            float4 av0 = *(const float4*)&As[kk][ty * 8];
            float4 av1 = *(const float4*)&As[kk][ty * 8 + 4];
            float4 bv = *(const float4*)&Bs[kk][tx * 4];
            float a[8] = {av0.x, av0.y, av0.z, av0.w, av1.x, av1.y, av1.z, av1.w};
            float b[4] = {bv.x, bv.y, bv.z, bv.w};
#pragma unroll
            for (int i = 0; i < 8; i++)
#pragma unroll
                for (int j = 0; j < 4; j++) acc[i][j] += a[i] * b[j];
        }
        __syncthreads();
    }
    int colb = bn0 + tx * 4;
    float4 bb = make_float4(0.f, 0.f, 0.f, 0.f);
    if (flags & 1) bb = *(const float4*)&bias[colb];
#pragma unroll
    for (int i = 0; i < 8; i++) {
        int row = bm0 + ty * 8 + i;
        float4 v = make_float4(acc[i][0] + bb.x, acc[i][1] + bb.y,
                               acc[i][2] + bb.z, acc[i][3] + bb.w);
        if (flags & 2) {
            v.x = fmaxf(v.x, 0.f); v.y = fmaxf(v.y, 0.f);
            v.z = fmaxf(v.z, 0.f); v.w = fmaxf(v.w, 0.f);
        }
        if (flags & 4) {
            float4 r = *(const float4*)&Rres[(size_t)row * N + colb];
            v.x += r.x; v.y += r.y; v.z += r.z; v.w += r.w;
        }
        *(float4*)&C[(size_t)row * N + colb] = v;
    }
}

// lm_w [128, V] -> transposed padded [NPAD, 128] fp16 (n-major)
__global__ void cvtb_k(const float* __restrict__ lm_w) {
    __shared__ float t[32][33];
    int n0 = blockIdx.x * 32, k0 = blockIdx.y * 32;
    int tx = threadIdx.x, ty = threadIdx.y;  // 32 x 8
    for (int i = ty; i < 32; i += 8) {
        int n = n0 + tx, k = k0 + i;
        t[i][tx] = (n < VV) ? lm_w[(size_t)k * VV + n] : 0.0f;
    }
    __syncthreads();
    for (int i = ty; i < 32; i += 8) {
        int n = n0 + i, k = k0 + tx;
        g_bh[(size_t)n * DD + k] = __float2half(t[tx][i]);
    }
}

// ---------------- mma / ldmatrix helpers ----------------
__device__ __forceinline__ uint32_t smem_u32(const void* p) {
    uint32_t a;
    asm("{ .reg .u64 t; cvta.to.shared.u64 t, %1; cvt.u32.u64 %0, t; }" : "=r"(a) : "l"(p));
    return a;
}
__device__ __forceinline__ void mma16816(float* c, const uint32_t* a,
                                         uint32_t b0, uint32_t b1) {
    asm volatile(
        "mma.sync.aligned.m16n8k16.row.col.f32.f16.f16.f32 "
        "{%0,%1,%2,%3}, {%4,%5,%6,%7}, {%8,%9}, {%0,%1,%2,%3};"
        : "+f"(c[0]), "+f"(c[1]), "+f"(c[2]), "+f"(c[3])
        : "r"(a[0]), "r"(a[1]), "r"(a[2]), "r"(a[3]), "r"(b0), "r"(b1));
}
__device__ __forceinline__ void ldsm4(uint32_t* r, uint32_t addr) {
    asm volatile("ldmatrix.sync.aligned.m8n8.x4.shared.b16 {%0,%1,%2,%3}, [%4];"
                 : "=r"(r[0]), "=r"(r[1]), "=r"(r[2]), "=r"(r[3]) : "r"(addr));
}

// ---------------- HMMA LM head (fp16, 2-term split, ldmatrix) ----------------
// CTA: 128(M) x 128(N), K = 2x128, 8 warps (4m x 2n), warp 32x64.
#define PADH 136                           // halves per padded row
#define ROWB (PADH * 2)                    // 272 bytes per row
#define ROWW (PADH / 2)                    // 68 words per row
#define AH_OFF 0
#define AL_OFF (128 * ROWB)                // 34816
#define BH_OFF (2 * 128 * ROWB)            // 69632
#define BIAS_OFF (3 * 128 * ROWB)          // 104448
#define LM_SMEM (BIAS_OFF + 128 * 4)       // 104960

__global__ void __launch_bounds__(256, 2) lmhead_k(
    const float* __restrict__ bias, float* __restrict__ C) {
    extern __shared__ __align__(16) char smem[];
    uint32_t smem_base = smem_u32(smem);
    int tid = threadIdx.x;
    int wid = tid >> 5;
    int lane = tid & 31;
    int g = lane >> 2;
    int t4 = lane & 3;
    int bm0 = blockIdx.x * 128;
    int bn0 = blockIdx.y * 128;
    int wm = (wid >> 1) * 32;     // warp M offset
    int wn = (wid & 1) * 64;      // warp N offset

    // ---- load tiles (row stride ROWB bytes) ----
    {
        const uint4* gah = (const uint4*)g_ah;
        const uint4* gal = (const uint4*)g_al;
        const uint4* gbh = (const uint4*)g_bh;
#pragma unroll
        for (int i = tid; i < 2048; i += 256) {
            int row = i >> 4, cb = i & 15;
            uint32_t so = (uint32_t)(row * ROWB + cb * 16);  // 8 halves = 16B
            size_t gi = (size_t)(bm0 + row) * 16 + cb;
            *(uint4*)(smem + AH_OFF + so) = gah[gi];
            *(uint4*)(smem + AL_OFF + so) = gal[gi];
            size_t gj = (size_t)(bn0 + row) * 16 + cb;
            *(uint4*)(smem + BH_OFF + so) = gbh[gj];
        }
        float* bs = (float*)(smem + BIAS_OFF);
        if (tid < 128) {
            int c = bn0 + tid;
            bs[tid] = (c < VV) ? bias[c] : 0.0f;
        }
    }
    __syncthreads();

    float acc[2][8][4];
#pragma unroll
    for (int i = 0; i < 2; i++)
#pragma unroll
        for (int j = 0; j < 8; j++)
#pragma unroll
            for (int q = 0; q < 4; q++) acc[i][j][q] = 0.0f;

    // ldmatrix lane addressing: lanes 0-15 -> rows 0-15 @k0, lanes 16-31 -> rows 0-15 @k8
    int lr = lane & 15;
    int lk = lane >> 4;
    uint32_t aoff = (uint32_t)((wm + lr) * ROWB + lk * 16);
    uint32_t a0hi = smem_base + AH_OFF + aoff;
    uint32_t a0lo = smem_base + AL_OFF + aoff;
    uint32_t bbase[4];
#pragma unroll
    for (int jp = 0; jp < 4; jp++)
        bbase[jp] = smem_base + BH_OFF + (uint32_t)((wn + jp * 16 + lr) * ROWB + lk * 16);

    // ---- mainloop: 2 split terms x 8 k-steps, no syncs ----
#pragma unroll 1
    for (int seg = 0; seg < 2; seg++) {
        uint32_t abase = seg ? a0lo : a0hi;
#pragma unroll
        for (int ks = 0; ks < 8; ks++) {
            uint32_t off = (uint32_t)ks * 32;  // 16 halves = 32 bytes per k-step
            uint32_t a0[4], a1[4];
            ldsm4(a0, abase + off);
            ldsm4(a1, abase + (uint32_t)(16 * ROWB) + off);
#pragma unroll
            for (int jp = 0; jp < 4; jp++) {
                uint32_t r[4];
                ldsm4(r, bbase[jp] + off);
                mma16816(acc[0][2 * jp],     a0, r[0], r[2]);
                mma16816(acc[0][2 * jp + 1], a0, r[1], r[3]);
                mma16816(acc[1][2 * jp],     a1, r[0], r[2]);
                mma16816(acc[1][2 * jp + 1], a1, r[1], r[3]);
            }
        }
    }

    // ---- epilogue: bias + scalar stores (VV odd -> no vector stores) + sum(exp) ----
    const float* bs = (const float*)(smem + BIAS_OFF);
    bool full = (bn0 + 128 <= VV);
#pragma unroll
    for (int i = 0; i < 2; i++) {
#pragma unroll
        for (int half = 0; half < 2; half++) {
            int gr = bm0 + wm + i * 16 + half * 8 + g;
            float* crow = C + (size_t)gr * VV + bn0;
            float s = 0.0f;
            if (full) {
#pragma unroll
                for (int j = 0; j < 8; j++) {
                    int lc = wn + j * 8 + 2 * t4;
                    float v0 = acc[i][j][half * 2 + 0] + bs[lc];
                    float v1 = acc[i][j][half * 2 + 1] + bs[lc + 1];
                    crow[lc] = v0;
                    crow[lc + 1] = v1;
                    s += __expf(v0) + __expf(v1);
                }
            } else {
#pragma unroll
                for (int j = 0; j < 8; j++) {
                    int lc = wn + j * 8 + 2 * t4;
                    int col = bn0 + lc;
                    float v0 = acc[i][j][half * 2 + 0] + bs[lc];
                    float v1 = acc[i][j][half * 2 + 1] + bs[lc + 1];
                    if (col < VV) { crow[lc] = v0; s += __expf(v0); }
                    if (col + 1 < VV) { crow[lc + 1] = v1; s += __expf(v1); }
                }
            }
            s += __shfl_xor_sync(0xffffffffu, s, 1);
            s += __shfl_xor_sync(0xffffffffu, s, 2);
            if (t4 == 0)
                g_part[(size_t)gr * NPART + blockIdx.y * 2 + (wid & 1)] = s;
        }
    }
}

// ---------------- NLL from partials ----------------
__global__ void nllred_k(const float* __restrict__ logits, const int* __restrict__ tgt) {
    int r = blockIdx.x;
    int tid = threadIdx.x;  // 128
    float s = 0.0f;
    for (int c = tid; c < NPART; c += 128) s += g_part[(size_t)r * NPART + c];
    __shared__ float red[4];
#pragma unroll
    for (int o = 16; o > 0; o >>= 1) s += __shfl_xor_sync(0xffffffffu, s, o);
    if ((tid & 31) == 0) red[tid >> 5] = s;
    __syncthreads();
    if (tid == 0) {
        float tot = red[0] + red[1] + red[2] + red[3];
        g_nll[r] = logf(tot) - logits[(size_t)r * VV + tgt[r]];
    }
}

__global__ void loss_k(float* __restrict__ out) {
    __shared__ float accs[256];
    float s = 0.0f;
    for (int i = threadIdx.x; i < BT; i += 256) s += g_nll[i];
    accs[threadIdx.x] = s;
    __syncthreads();
    for (int o = 128; o > 0; o >>= 1) {
        if (threadIdx.x < o) accs[threadIdx.x] += accs[threadIdx.x + o];
        __syncthreads();
    }
    if (threadIdx.x == 0) out[0] = accs[0] * (1.0f / BT);
}

// ---------------- host launcher ----------------
static void launch_gemm64(const float* A, const float* B, const float* bias,
                          const float* res, float* C, int M, int N, int K, int flags) {
    dim3 grid(N / 64, M / 64);
    gemm64_k<<<grid, 128>>>(A, B, bias, res, C, M, N, K, flags);
}

extern "C" void kernel_launch(void* const* d_in, const int* in_sizes, int n_in,
                              void* d_out, int out_size) {
    const int* idx       = (const int*)d_in[0];
    const int* targets   = (const int*)d_in[1];
    const float* tok_emb = (const float*)d_in[2];
    const float* pos_emb = (const float*)d_in[3];
    const float* wq      = (const float*)d_in[4];
    const float* wk      = (const float*)d_in[5];
    const float* wv      = (const float*)d_in[6];
    const float* wproj   = (const float*)d_in[7];
    const float* bproj   = (const float*)d_in[8];
    const float* w1      = (const float*)d_in[9];
    const float* b1      = (const float*)d_in[10];
    const float* w2      = (const float*)d_in[11];
    const float* b2      = (const float*)d_in[12];
    const float* ln1_g   = (const float*)d_in[13];
    const float* ln1_b   = (const float*)d_in[14];
    const float* ln2_g   = (const float*)d_in[15];
    const float* ln2_b   = (const float*)d_in[16];
    const float* lnf_g   = (const float*)d_in[17];
    const float* lnf_b   = (const float*)d_in[18];
    const float* lm_w    = (const float*)d_in[19];
    const float* lm_b    = (const float*)d_in[20];
    float* out = (float*)d_out;

    float *px, *ph, *pqkv, *po, *pm, *pwqkv;
    cudaGetSymbolAddress((void**)&px, g_x);
    cudaGetSymbolAddress((void**)&ph, g_h);
    cudaGetSymbolAddress((void**)&pqkv, g_qkv);
    cudaGetSymbolAddress((void**)&po, g_o);
    cudaGetSymbolAddress((void**)&pm, g_m);
    cudaGetSymbolAddress((void**)&pwqkv, g_wqkv);

    cudaFuncSetAttribute(lmhead_k, cudaFuncAttributeMaxDynamicSharedMemorySize, LM_SMEM);

    embed_k<<<BT, DD>>>(idx, tok_emb, pos_emb);
    repack_k<<<(LL * DD * DD + 255) / 256, 256>>>(wq, wk, wv);
    cvtb_k<<<dim3(NPAD / 32, 4), dim3(32, 8)>>>(lm_w);

    for (int l = 0; l < LL; l++) {
        ln_k<<<BT, DD>>>(px, ph, ln1_g + l * DD, ln1_b + l * DD);
        launch_gemm64(ph, pwqkv + (size_t)l * DD * 384, nullptr, nullptr,
                      pqkv, BT, 384, DD, 0);
        attn_k<<<BB * HH, TT>>>();
        launch_gemm64(po, wproj + (size_t)l * DD * DD, bproj + l * DD, px, px,
                      BT, DD, DD, 1 | 4);
        ln_k<<<BT, DD>>>(px, ph, ln2_g + l * DD, ln2_b + l * DD);
        launch_gemm64(ph, w1 + (size_t)l * DD * DFF, b1 + l * DFF, nullptr,
                      pm, BT, DFF, DD, 1 | 2);
        launch_gemm64(pm, w2 + (size_t)l * DFF * DD, b2 + l * DD, px, px,
                      BT, DD, DFF, 1 | 4);
    }

    lnsplit_k<<<BT, DD>>>(px, lnf_g, lnf_b);

    dim3 lgrid(BT / 128, NBLK);
    lmhead_k<<<lgrid, 256, LM_SMEM>>>(lm_b, out);

    nllred_k<<<BT, 128>>>(out, targets);
    if (out_size > BT * VV) {
        loss_k<<<1, 256>>>(out + (size_t)BT * VV);
    }
}

// round 10
// speedup vs baseline: 3.1985x; 1.0373x over previous
#include <cuda_runtime.h>
#include <cuda_bf16.h>
#include <cuda_fp16.h>
#include <math.h>
#include <stdint.h>

#define BB 32
#define TT 128
#define DD 128
#define HH 8
#define HD 16
#define LL 4
#define VV 50257
#define BT (BB * TT)       // 4096
#define DFF (4 * DD)       // 512
#define NBLK 393                 // ceil(VV / 128)
#define NPART (NBLK * 2)         // 786 partial slots per row
#define NPAD (NBLK * 128)        // 50304

// ---------------- scratch ----------------
__device__ float g_x[BT * DD];
__device__ float g_qkv[BT * 384];
__device__ float g_o[BT * DD];
__device__ float g_m[BT * DFF];
__device__ float g_wqkv[LL * DD * 384];
__device__ float g_part[(size_t)BT * NPART];
__device__ float g_nll[BT];
__device__ __half g_ah[BT * DD];
__device__ __half g_bh[(size_t)NPAD * DD];

// ---------------- embedding ----------------
__global__ void embed_k(const int* __restrict__ idx,
                        const float* __restrict__ tok,
                        const float* __restrict__ pos) {
    int m = blockIdx.x;
    int d = threadIdx.x;
    int t = m & (TT - 1);
    g_x[m * DD + d] = tok[(size_t)idx[m] * DD + d] + pos[t * DD + d];
}

// ---------------- repack qkv weights [L,H,D,HD] -> [L, D, 384] ----------------
__global__ void repack_k(const float* __restrict__ wq,
                         const float* __restrict__ wk,
                         const float* __restrict__ wv) {
    int o = blockIdx.x * blockDim.x + threadIdx.x;
    if (o >= LL * DD * DD) return;
    int l = o >> 14;
    int rem = o & 16383;
    int d = rem >> 7;
    int n = rem & 127;
    int h = n >> 4;
    int e = n & 15;
    int in = ((l * HH + h) * DD + d) * HD + e;
    float* W = g_wqkv + (size_t)l * DD * 384 + d * 384;
    W[n]       = wq[in];
    W[128 + n] = wk[in];
    W[256 + n] = wv[in];
}

// ---------------- final LN fused with fp16 convert ----------------
__global__ void lncvt_k(const float* __restrict__ in,
                        const float* __restrict__ gam, const float* __restrict__ bet) {
    __shared__ float red[4];
    int m = blockIdx.x, d = threadIdx.x;
    int i = m * DD + d;
    float x = in[i];
    float s = x;
#pragma unroll
    for (int o = 16; o > 0; o >>= 1) s += __shfl_xor_sync(0xffffffffu, s, o);
    if ((d & 31) == 0) red[d >> 5] = s;
    __syncthreads();
    float mean = (red[0] + red[1] + red[2] + red[3]) * (1.0f / DD);
    __syncthreads();
    float c = x - mean;
    float cs = c * c;
#pragma unroll
    for (int o = 16; o > 0; o >>= 1) cs += __shfl_xor_sync(0xffffffffu, cs, o);
    if ((d & 31) == 0) red[d >> 5] = cs;
    __syncthreads();
    float var = (red[0] + red[1] + red[2] + red[3]) * (1.0f / DD);
    float y = c * rsqrtf(var + 1e-5f) * gam[d] + bet[d];
    g_ah[i] = __float2half(y);
}

// ---------------- attention ----------------
__global__ void attn_k() {
    int b = blockIdx.x / HH;
    int h = blockIdx.x % HH;
    int t = threadIdx.x;
    __shared__ float ks[TT][HD];
    __shared__ float vs[TT][HD];
    const float* rowp = g_qkv + (size_t)(b * TT + t) * 384 + h * HD;
#pragma unroll
    for (int e = 0; e < HD; e++) {
        ks[t][e] = rowp[128 + e];
        vs[t][e] = rowp[256 + e];
    }
    __syncthreads();
    float q[HD];
#pragma unroll
    for (int e = 0; e < HD; e++) q[e] = rowp[e];

    const float scale = 0.08838834764831845f;  // 1/sqrt(128)
    float mrun = -1e30f, lrun = 0.0f;
    float acc[HD];
#pragma unroll
    for (int e = 0; e < HD; e++) acc[e] = 0.0f;
    for (int s = 0; s <= t; s++) {
        float d = 0.0f;
#pragma unroll
        for (int e = 0; e < HD; e++) d += q[e] * ks[s][e];
        d *= scale;
        float mn = fmaxf(mrun, d);
        float corr = __expf(mrun - mn);
        float p = __expf(d - mn);
        lrun = lrun * corr + p;
#pragma unroll
        for (int e = 0; e < HD; e++) acc[e] = acc[e] * corr + p * vs[s][e];
        mrun = mn;
    }
    float inv = 1.0f / lrun;
#pragma unroll
    for (int e = 0; e < HD; e++)
        g_o[(size_t)(b * TT + t) * DD + h * HD + e] = acc[e] * inv;
}

// ---------------- body GEMM: 64x64 tiles, 128 threads ----------------
__global__ void __launch_bounds__(128) gemm64_k(
    const float* __restrict__ A, const float* __restrict__ Bm,
    const float* __restrict__ bias, const float* __restrict__ Rres,
    float* __restrict__ C, int M, int N, int K, int flags) {
    __shared__ float As[16][64];
    __shared__ float Bs[16][64];
    int bm0 = blockIdx.y * 64;
    int bn0 = blockIdx.x * 64;
    int tid = threadIdx.x;
    int ty = tid >> 4;
    int tx = tid & 15;

    float acc[8][4];
#pragma unroll
    for (int i = 0; i < 8; i++)
#pragma unroll
        for (int j = 0; j < 4; j++) acc[i][j] = 0.0f;

    int ar = tid >> 1;
    int ac = (tid & 1) * 8;
    int br = tid >> 3;
    int bc = (tid & 7) * 8;

    for (int k0 = 0; k0 < K; k0 += 16) {
        float4 a0 = *(const float4*)&A[(size_t)(bm0 + ar) * K + k0 + ac];
        float4 a1 = *(const float4*)&A[(size_t)(bm0 + ar) * K + k0 + ac + 4];
        As[ac + 0][ar] = a0.x; As[ac + 1][ar] = a0.y;
        As[ac + 2][ar] = a0.z; As[ac + 3][ar] = a0.w;
        As[ac + 4][ar] = a1.x; As[ac + 5][ar] = a1.y;
        As[ac + 6][ar] = a1.z; As[ac + 7][ar] = a1.w;
        float4 b0 = *(const float4*)&Bm[(size_t)(k0 + br) * N + bn0 + bc];
        float4 b1 = *(const float4*)&Bm[(size_t)(k0 + br) * N + bn0 + bc + 4];
        *(float4*)&Bs[br][bc] = b0;
        *(float4*)&Bs[br][bc + 4] = b1;
        __syncthreads();
#pragma unroll
        for (int kk = 0; kk < 16; kk++) {
            float4 av0 = *(const float4*)&As[kk][ty * 8];
            float4 av1 = *(const float4*)&As[kk][ty * 8 + 4];
            float4 bv = *(const float4*)&Bs[kk][tx * 4];
            float a[8] = {av0.x, av0.y, av0.z, av0.w, av1.x, av1.y, av1.z, av1.w};
            float b[4] = {bv.x, bv.y, bv.z, bv.w};
#pragma unroll
            for (int i = 0; i < 8; i++)
#pragma unroll
                for (int j = 0; j < 4; j++) acc[i][j] += a[i] * b[j];
        }
        __syncthreads();
    }
    int colb = bn0 + tx * 4;
    float4 bb = make_float4(0.f, 0.f, 0.f, 0.f);
    if (flags & 1) bb = *(const float4*)&bias[colb];
#pragma unroll
    for (int i = 0; i < 8; i++) {
        int row = bm0 + ty * 8 + i;
        float4 v = make_float4(acc[i][0] + bb.x, acc[i][1] + bb.y,
                               acc[i][2] + bb.z, acc[i][3] + bb.w);
        if (flags & 2) {
            v.x = fmaxf(v.x, 0.f); v.y = fmaxf(v.y, 0.f);
            v.z = fmaxf(v.z, 0.f); v.w = fmaxf(v.w, 0.f);
        }
        if (flags & 4) {
            float4 r = *(const float4*)&Rres[(size_t)row * N + colb];
            v.x += r.x; v.y += r.y; v.z += r.z; v.w += r.w;
        }
        *(float4*)&C[(size_t)row * N + colb] = v;
    }
}

// ---------------- fused LN + GEMM: C = LN(A) @ B  (K=128 fixed) ----------------
// flags: 1=bias, 2=relu
__global__ void __launch_bounds__(128) lngemm_k(
    const float* __restrict__ A, const float* __restrict__ Bm,
    const float* __restrict__ gam, const float* __restrict__ bet,
    const float* __restrict__ bias, float* __restrict__ C,
    int N, int flags) {
    __shared__ float As[16][64];
    __shared__ float Bs[16][64];
    __shared__ float mean_s[64], rstd_s[64];
    __shared__ float gb[256];  // gam[0..127], bet[128..255]
    int bm0 = blockIdx.y * 64;
    int bn0 = blockIdx.x * 64;
    int tid = threadIdx.x;
    int ty = tid >> 4;
    int tx = tid & 15;

    gb[tid] = gam[tid];        // blockDim = 128
    gb[128 + tid] = bet[tid];

    // ---- row stats: 2 threads per row, 64 elems each ----
    {
        int rm = tid >> 1, hf = tid & 1;
        const float4* Ar = (const float4*)(A + (size_t)(bm0 + rm) * DD + hf * 64);
        float s = 0.0f, s2 = 0.0f;
#pragma unroll
        for (int i = 0; i < 16; i++) {
            float4 v = Ar[i];
            s += v.x + v.y + v.z + v.w;
            s2 += v.x * v.x + v.y * v.y + v.z * v.z + v.w * v.w;
        }
        s += __shfl_xor_sync(0xffffffffu, s, 1);
        s2 += __shfl_xor_sync(0xffffffffu, s2, 1);
        if (hf == 0) {
            float mn = s * (1.0f / DD);
            mean_s[rm] = mn;
            rstd_s[rm] = rsqrtf(s2 * (1.0f / DD) - mn * mn + 1e-5f);
        }
    }
    __syncthreads();

    float acc[8][4];
#pragma unroll
    for (int i = 0; i < 8; i++)
#pragma unroll
        for (int j = 0; j < 4; j++) acc[i][j] = 0.0f;

    int ar = tid >> 1;
    int ac = (tid & 1) * 8;
    int br = tid >> 3;
    int bc = (tid & 7) * 8;
    float mu = mean_s[ar], rs = rstd_s[ar];

    for (int k0 = 0; k0 < DD; k0 += 16) {
        float4 a0 = *(const float4*)&A[(size_t)(bm0 + ar) * DD + k0 + ac];
        float4 a1 = *(const float4*)&A[(size_t)(bm0 + ar) * DD + k0 + ac + 4];
        float va[8] = {a0.x, a0.y, a0.z, a0.w, a1.x, a1.y, a1.z, a1.w};
#pragma unroll
        for (int j = 0; j < 8; j++) {
            int k = k0 + ac + j;
            As[ac + j][ar] = (va[j] - mu) * rs * gb[k] + gb[128 + k];
        }
        float4 b0 = *(const float4*)&Bm[(size_t)(k0 + br) * N + bn0 + bc];
        float4 b1 = *(const float4*)&Bm[(size_t)(k0 + br) * N + bn0 + bc + 4];
        *(float4*)&Bs[br][bc] = b0;
        *(float4*)&Bs[br][bc + 4] = b1;
        __syncthreads();
#pragma unroll
        for (int kk = 0; kk < 16; kk++) {
            float4 av0 = *(const float4*)&As[kk][ty * 8];
            float4 av1 = *(const float4*)&As[kk][ty * 8 + 4];
            float4 bv = *(const float4*)&Bs[kk][tx * 4];
            float a[8] = {av0.x, av0.y, av0.z, av0.w, av1.x, av1.y, av1.z, av1.w};
            float b[4] = {bv.x, bv.y, bv.z, bv.w};
#pragma unroll
            for (int i = 0; i < 8; i++)
#pragma unroll
                for (int j = 0; j < 4; j++) acc[i][j] += a[i] * b[j];
        }
        __syncthreads();
    }
    int colb = bn0 + tx * 4;
    float4 bb = make_float4(0.f, 0.f, 0.f, 0.f);
    if (flags & 1) bb = *(const float4*)&bias[colb];
#pragma unroll
    for (int i = 0; i < 8; i++) {
        int row = bm0 + ty * 8 + i;
        float4 v = make_float4(acc[i][0] + bb.x, acc[i][1] + bb.y,
                               acc[i][2] + bb.z, acc[i][3] + bb.w);
        if (flags & 2) {
            v.x = fmaxf(v.x, 0.f); v.y = fmaxf(v.y, 0.f);
            v.z = fmaxf(v.z, 0.f); v.w = fmaxf(v.w, 0.f);
        }
        *(float4*)&C[(size_t)row * N + colb] = v;
    }
}

// lm_w [128, V] -> transposed padded [NPAD, 128] fp16 (n-major)
__global__ void cvtb_k(const float* __restrict__ lm_w) {
    __shared__ float t[32][33];
    int n0 = blockIdx.x * 32, k0 = blockIdx.y * 32;
    int tx = threadIdx.x, ty = threadIdx.y;  // 32 x 8
    for (int i = ty; i < 32; i += 8) {
        int n = n0 + tx, k = k0 + i;
        t[i][tx] = (n < VV) ? lm_w[(size_t)k * VV + n] : 0.0f;
    }
    __syncthreads();
    for (int i = ty; i < 32; i += 8) {
        int n = n0 + i, k = k0 + tx;
        g_bh[(size_t)n * DD + k] = __float2half(t[tx][i]);
    }
}

// ---------------- mma / ldmatrix helpers ----------------
__device__ __forceinline__ uint32_t smem_u32(const void* p) {
    uint32_t a;
    asm("{ .reg .u64 t; cvta.to.shared.u64 t, %1; cvt.u32.u64 %0, t; }" : "=r"(a) : "l"(p));
    return a;
}
__device__ __forceinline__ void mma16816(float* c, const uint32_t* a,
                                         uint32_t b0, uint32_t b1) {
    asm volatile(
        "mma.sync.aligned.m16n8k16.row.col.f32.f16.f16.f32 "
        "{%0,%1,%2,%3}, {%4,%5,%6,%7}, {%8,%9}, {%0,%1,%2,%3};"
        : "+f"(c[0]), "+f"(c[1]), "+f"(c[2]), "+f"(c[3])
        : "r"(a[0]), "r"(a[1]), "r"(a[2]), "r"(a[3]), "r"(b0), "r"(b1));
}
__device__ __forceinline__ void ldsm4(uint32_t* r, uint32_t addr) {
    asm volatile("ldmatrix.sync.aligned.m8n8.x4.shared.b16 {%0,%1,%2,%3}, [%4];"
                 : "=r"(r[0]), "=r"(r[1]), "=r"(r[2]), "=r"(r[3]) : "r"(addr));
}

// ---------------- HMMA LM head (pure fp16, ldmatrix) ----------------
// CTA: 128(M) x 128(N), K = 128, 8 warps (4m x 2n), warp 32x64.
#define PADH 136                           // halves per padded row
#define ROWB (PADH * 2)                    // 272 bytes per row
#define AH_OFF 0
#define BH_OFF (128 * ROWB)                // 34816
#define BIAS_OFF (2 * 128 * ROWB)          // 69632
#define LM_SMEM (BIAS_OFF + 128 * 4)       // 70144

__global__ void __launch_bounds__(256, 3) lmhead_k(
    const float* __restrict__ bias, float* __restrict__ C) {
    extern __shared__ __align__(16) char smem[];
    uint32_t smem_base = smem_u32(smem);
    int tid = threadIdx.x;
    int wid = tid >> 5;
    int lane = tid & 31;
    int g = lane >> 2;
    int t4 = lane & 3;
    int bm0 = blockIdx.x * 128;
    int bn0 = blockIdx.y * 128;
    int wm = (wid >> 1) * 32;     // warp M offset
    int wn = (wid & 1) * 64;      // warp N offset

    // ---- load tiles (row stride ROWB bytes) ----
    {
        const uint4* gah = (const uint4*)g_ah;
        const uint4* gbh = (const uint4*)g_bh;
#pragma unroll
        for (int i = tid; i < 2048; i += 256) {
            int row = i >> 4, cb = i & 15;
            uint32_t so = (uint32_t)(row * ROWB + cb * 16);  // 8 halves = 16B
            *(uint4*)(smem + AH_OFF + so) = gah[(size_t)(bm0 + row) * 16 + cb];
            *(uint4*)(smem + BH_OFF + so) = gbh[(size_t)(bn0 + row) * 16 + cb];
        }
        float* bs = (float*)(smem + BIAS_OFF);
        if (tid < 128) {
            int c = bn0 + tid;
            bs[tid] = (c < VV) ? bias[c] : 0.0f;
        }
    }
    __syncthreads();

    float acc[2][8][4];
#pragma unroll
    for (int i = 0; i < 2; i++)
#pragma unroll
        for (int j = 0; j < 8; j++)
#pragma unroll
            for (int q = 0; q < 4; q++) acc[i][j][q] = 0.0f;

    int lr = lane & 15;
    int lk = lane >> 4;
    uint32_t abase = smem_base + AH_OFF + (uint32_t)((wm + lr) * ROWB + lk * 16);
    uint32_t bbase[4];
#pragma unroll
    for (int jp = 0; jp < 4; jp++)
        bbase[jp] = smem_base + BH_OFF + (uint32_t)((wn + jp * 16 + lr) * ROWB + lk * 16);

    // ---- mainloop: 8 k-steps, no syncs ----
#pragma unroll
    for (int ks = 0; ks < 8; ks++) {
        uint32_t off = (uint32_t)ks * 32;  // 16 halves = 32 bytes per k-step
        uint32_t a0[4], a1[4];
        ldsm4(a0, abase + off);
        ldsm4(a1, abase + (uint32_t)(16 * ROWB) + off);
#pragma unroll
        for (int jp = 0; jp < 4; jp++) {
            uint32_t r[4];
            ldsm4(r, bbase[jp] + off);
            mma16816(acc[0][2 * jp],     a0, r[0], r[2]);
            mma16816(acc[0][2 * jp + 1], a0, r[1], r[3]);
            mma16816(acc[1][2 * jp],     a1, r[0], r[2]);
            mma16816(acc[1][2 * jp + 1], a1, r[1], r[3]);
        }
    }

    // ---- epilogue: bias + scalar stores (VV odd) + sum(exp) partials ----
    const float* bs = (const float*)(smem + BIAS_OFF);
    bool full = (bn0 + 128 <= VV);
#pragma unroll
    for (int i = 0; i < 2; i++) {
#pragma unroll
        for (int half = 0; half < 2; half++) {
            int gr = bm0 + wm + i * 16 + half * 8 + g;
            float* crow = C + (size_t)gr * VV + bn0;
            float s = 0.0f;
            if (full) {
#pragma unroll
                for (int j = 0; j < 8; j++) {
                    int lc = wn + j * 8 + 2 * t4;
                    float v0 = acc[i][j][half * 2 + 0] + bs[lc];
                    float v1 = acc[i][j][half * 2 + 1] + bs[lc + 1];
                    crow[lc] = v0;
                    crow[lc + 1] = v1;
                    s += __expf(v0) + __expf(v1);
                }
            } else {
#pragma unroll
                for (int j = 0; j < 8; j++) {
                    int lc = wn + j * 8 + 2 * t4;
                    int col = bn0 + lc;
                    float v0 = acc[i][j][half * 2 + 0] + bs[lc];
                    float v1 = acc[i][j][half * 2 + 1] + bs[lc + 1];
                    if (col < VV) { crow[lc] = v0; s += __expf(v0); }
                    if (col + 1 < VV) { crow[lc + 1] = v1; s += __expf(v1); }
                }
            }
            s += __shfl_xor_sync(0xffffffffu, s, 1);
            s += __shfl_xor_sync(0xffffffffu, s, 2);
            if (t4 == 0)
                g_part[(size_t)gr * NPART + blockIdx.y * 2 + (wid & 1)] = s;
        }
    }
}

// ---------------- NLL from partials ----------------
__global__ void nllred_k(const float* __restrict__ logits, const int* __restrict__ tgt) {
    int r = blockIdx.x;
    int tid = threadIdx.x;  // 128
    float s = 0.0f;
    for (int c = tid; c < NPART; c += 128) s += g_part[(size_t)r * NPART + c];
    __shared__ float red[4];
#pragma unroll
    for (int o = 16; o > 0; o >>= 1) s += __shfl_xor_sync(0xffffffffu, s, o);
    if ((tid & 31) == 0) red[tid >> 5] = s;
    __syncthreads();
    if (tid == 0) {
        float tot = red[0] + red[1] + red[2] + red[3];
        g_nll[r] = logf(tot) - logits[(size_t)r * VV + tgt[r]];
    }
}

__global__ void loss_k(float* __restrict__ out) {
    __shared__ float accs[256];
    float s = 0.0f;
    for (int i = threadIdx.x; i < BT; i += 256) s += g_nll[i];
    accs[threadIdx.x] = s;
    __syncthreads();
    for (int o = 128; o > 0; o >>= 1) {
        if (threadIdx.x < o) accs[threadIdx.x] += accs[threadIdx.x + o];
        __syncthreads();
    }
    if (threadIdx.x == 0) out[0] = accs[0] * (1.0f / BT);
}

// ---------------- host launcher ----------------
static void launch_gemm64(const float* A, const float* B, const float* bias,
                          const float* res, float* C, int M, int N, int K, int flags) {
    dim3 grid(N / 64, M / 64);
    gemm64_k<<<grid, 128>>>(A, B, bias, res, C, M, N, K, flags);
}

extern "C" void kernel_launch(void* const* d_in, const int* in_sizes, int n_in,
                              void* d_out, int out_size) {
    const int* idx       = (const int*)d_in[0];
    const int* targets   = (const int*)d_in[1];
    const float* tok_emb = (const float*)d_in[2];
    const float* pos_emb = (const float*)d_in[3];
    const float* wq      = (const float*)d_in[4];
    const float* wk      = (const float*)d_in[5];
    const float* wv      = (const float*)d_in[6];
    const float* wproj   = (const float*)d_in[7];
    const float* bproj   = (const float*)d_in[8];
    const float* w1      = (const float*)d_in[9];
    const float* b1      = (const float*)d_in[10];
    const float* w2      = (const float*)d_in[11];
    const float* b2      = (const float*)d_in[12];
    const float* ln1_g   = (const float*)d_in[13];
    const float* ln1_b   = (const float*)d_in[14];
    const float* ln2_g   = (const float*)d_in[15];
    const float* ln2_b   = (const float*)d_in[16];
    const float* lnf_g   = (const float*)d_in[17];
    const float* lnf_b   = (const float*)d_in[18];
    const float* lm_w    = (const float*)d_in[19];
    const float* lm_b    = (const float*)d_in[20];
    float* out = (float*)d_out;

    float *px, *pqkv, *po, *pm, *pwqkv;
    cudaGetSymbolAddress((void**)&px, g_x);
    cudaGetSymbolAddress((void**)&pqkv, g_qkv);
    cudaGetSymbolAddress((void**)&po, g_o);
    cudaGetSymbolAddress((void**)&pm, g_m);
    cudaGetSymbolAddress((void**)&pwqkv, g_wqkv);

    cudaFuncSetAttribute(lmhead_k, cudaFuncAttributeMaxDynamicSharedMemorySize, LM_SMEM);

    embed_k<<<BT, DD>>>(idx, tok_emb, pos_emb);
    repack_k<<<(LL * DD * DD + 255) / 256, 256>>>(wq, wk, wv);
    cvtb_k<<<dim3(NPAD / 32, 4), dim3(32, 8)>>>(lm_w);

    for (int l = 0; l < LL; l++) {
        // fused LN1 + QKV gemm
        lngemm_k<<<dim3(384 / 64, BT / 64), 128>>>(
            px, pwqkv + (size_t)l * DD * 384, ln1_g + l * DD, ln1_b + l * DD,
            nullptr, pqkv, 384, 0);
        attn_k<<<BB * HH, TT>>>();
        launch_gemm64(po, wproj + (size_t)l * DD * DD, bproj + l * DD, px, px,
                      BT, DD, DD, 1 | 4);
        // fused LN2 + MLP1 gemm (bias+relu)
        lngemm_k<<<dim3(DFF / 64, BT / 64), 128>>>(
            px, w1 + (size_t)l * DD * DFF, ln2_g + l * DD, ln2_b + l * DD,
            b1 + l * DFF, pm, DFF, 1 | 2);
        launch_gemm64(pm, w2 + (size_t)l * DFF * DD, b2 + l * DD, px, px,
                      BT, DD, DFF, 1 | 4);
    }

    lncvt_k<<<BT, DD>>>(px, lnf_g, lnf_b);

    dim3 lgrid(BT / 128, NBLK);
    lmhead_k<<<lgrid, 256, LM_SMEM>>>(lm_b, out);

    nllred_k<<<BT, 128>>>(out, targets);
    if (out_size > BT * VV) {
        loss_k<<<1, 256>>>(out + (size_t)BT * VV);
    }
}

// round 11
// speedup vs baseline: 3.4646x; 1.0832x over previous
#include <cuda_runtime.h>
#include <cuda_bf16.h>
#include <cuda_fp16.h>
#include <math.h>
#include <stdint.h>

#define BB 32
#define TT 128
#define DD 128
#define HH 8
#define HD 16
#define LL 4
#define VV 50257
#define BT (BB * TT)       // 4096
#define DFF (4 * DD)       // 512
#define NBLK 393                 // ceil(VV / 128)
#define NPART (NBLK * 2)         // 786 partial slots per row
#define NPAD (NBLK * 128)        // 50304

// ---------------- scratch ----------------
__device__ float g_x[BT * DD];
__device__ float g_qkv[BT * 384];
__device__ float g_o[BT * DD];
__device__ float g_m[BT * DFF];
__device__ float g_part[(size_t)BT * NPART];
__device__ float g_nll[BT];
__device__ __half g_ah[BT * DD];
__device__ __half g_bh[(size_t)NPAD * DD];
// body weights, n-major [N][K] fp16 hi/lo
__device__ __half g_wqkvh[LL * 384 * DD], g_wqkvl[LL * 384 * DD];
__device__ __half g_wph[LL * DD * DD],   g_wpl[LL * DD * DD];
__device__ __half g_w1h[LL * DFF * DD],  g_w1l[LL * DFF * DD];
__device__ __half g_w2h[LL * DD * DFF],  g_w2l[LL * DD * DFF];

// ---------------- helpers ----------------
__device__ __forceinline__ uint32_t smem_u32(const void* p) {
    uint32_t a;
    asm("{ .reg .u64 t; cvta.to.shared.u64 t, %1; cvt.u32.u64 %0, t; }" : "=r"(a) : "l"(p));
    return a;
}
__device__ __forceinline__ void mma16816(float* c, const uint32_t* a,
                                         uint32_t b0, uint32_t b1) {
    asm volatile(
        "mma.sync.aligned.m16n8k16.row.col.f32.f16.f16.f32 "
        "{%0,%1,%2,%3}, {%4,%5,%6,%7}, {%8,%9}, {%0,%1,%2,%3};"
        : "+f"(c[0]), "+f"(c[1]), "+f"(c[2]), "+f"(c[3])
        : "r"(a[0]), "r"(a[1]), "r"(a[2]), "r"(a[3]), "r"(b0), "r"(b1));
}
__device__ __forceinline__ void ldsm4(uint32_t* r, uint32_t addr) {
    asm volatile("ldmatrix.sync.aligned.m8n8.x4.shared.b16 {%0,%1,%2,%3}, [%4];"
                 : "=r"(r[0]), "=r"(r[1]), "=r"(r[2]), "=r"(r[3]) : "r"(addr));
}

// ---------------- embedding ----------------
__global__ void embed_k(const int* __restrict__ idx,
                        const float* __restrict__ tok,
                        const float* __restrict__ pos) {
    int m = blockIdx.x;
    int d = threadIdx.x;
    int t = m & (TT - 1);
    g_x[m * DD + d] = tok[(size_t)idx[m] * DD + d] + pos[t * DD + d];
}

// ---------------- qkv weights [L,H,D,HD] -> n-major [L][384][128] fp16 hi/lo ----------------
__global__ void cvtwqkv_k(const float* __restrict__ wq,
                          const float* __restrict__ wk,
                          const float* __restrict__ wv) {
    int o = blockIdx.x * 256 + threadIdx.x;
    if (o >= LL * 384 * DD) return;
    int l = o / (384 * DD);
    int rem = o % (384 * DD);
    int n = rem >> 7, d = rem & 127;
    int which = n >> 7;
    int nn = n & 127;
    int h = nn >> 4, e = nn & 15;
    const float* W = (which == 0) ? wq : (which == 1) ? wk : wv;
    float x = W[(((size_t)l * HH + h) * DD + d) * HD + e];
    __half hi = __float2half(x);
    g_wqkvh[o] = hi;
    g_wqkvl[o] = __float2half(x - __half2float(hi));
}

// ---------------- generic weight transpose-convert: W[l][K][N] -> [l][N][K] hi/lo ----------------
__global__ void cvtw_k(const float* __restrict__ W, __half* __restrict__ oh,
                       __half* __restrict__ ol, int K, int N) {
    __shared__ float t[32][33];
    int l = blockIdx.z;
    const float* Wl = W + (size_t)l * K * N;
    __half* ohl = oh + (size_t)l * N * K;
    __half* oll = ol + (size_t)l * N * K;
    int n0 = blockIdx.x * 32, k0 = blockIdx.y * 32;
    int tx = threadIdx.x, ty = threadIdx.y;  // 32 x 8
    for (int i = ty; i < 32; i += 8)
        t[i][tx] = Wl[(size_t)(k0 + i) * N + n0 + tx];
    __syncthreads();
    for (int i = ty; i < 32; i += 8) {
        int n = n0 + i, k = k0 + tx;
        float x = t[tx][i];
        __half hi = __float2half(x);
        ohl[(size_t)n * K + k] = hi;
        oll[(size_t)n * K + k] = __float2half(x - __half2float(hi));
    }
}

// ---------------- final LN fused with fp16 convert ----------------
__global__ void lncvt_k(const float* __restrict__ in,
                        const float* __restrict__ gam, const float* __restrict__ bet) {
    __shared__ float red[4];
    int m = blockIdx.x, d = threadIdx.x;
    int i = m * DD + d;
    float x = in[i];
    float s = x;
#pragma unroll
    for (int o = 16; o > 0; o >>= 1) s += __shfl_xor_sync(0xffffffffu, s, o);
    if ((d & 31) == 0) red[d >> 5] = s;
    __syncthreads();
    float mean = (red[0] + red[1] + red[2] + red[3]) * (1.0f / DD);
    __syncthreads();
    float c = x - mean;
    float cs = c * c;
#pragma unroll
    for (int o = 16; o > 0; o >>= 1) cs += __shfl_xor_sync(0xffffffffu, cs, o);
    if ((d & 31) == 0) red[d >> 5] = cs;
    __syncthreads();
    float var = (red[0] + red[1] + red[2] + red[3]) * (1.0f / DD);
    float y = c * rsqrtf(var + 1e-5f) * gam[d] + bet[d];
    g_ah[i] = __float2half(y);
}

// ---------------- attention ----------------
__global__ void attn_k() {
    int b = blockIdx.x / HH;
    int h = blockIdx.x % HH;
    int t = threadIdx.x;
    __shared__ float ks[TT][HD];
    __shared__ float vs[TT][HD];
    const float* rowp = g_qkv + (size_t)(b * TT + t) * 384 + h * HD;
#pragma unroll
    for (int e = 0; e < HD; e++) {
        ks[t][e] = rowp[128 + e];
        vs[t][e] = rowp[256 + e];
    }
    __syncthreads();
    float q[HD];
#pragma unroll
    for (int e = 0; e < HD; e++) q[e] = rowp[e];

    const float scale = 0.08838834764831845f;  // 1/sqrt(128)
    float mrun = -1e30f, lrun = 0.0f;
    float acc[HD];
#pragma unroll
    for (int e = 0; e < HD; e++) acc[e] = 0.0f;
    for (int s = 0; s <= t; s++) {
        float d = 0.0f;
#pragma unroll
        for (int e = 0; e < HD; e++) d += q[e] * ks[s][e];
        d *= scale;
        float mn = fmaxf(mrun, d);
        float corr = __expf(mrun - mn);
        float p = __expf(d - mn);
        lrun = lrun * corr + p;
#pragma unroll
        for (int e = 0; e < HD; e++) acc[e] = acc[e] * corr + p * vs[s][e];
        mrun = mn;
    }
    float inv = 1.0f / lrun;
#pragma unroll
    for (int e = 0; e < HD; e++)
        g_o[(size_t)(b * TT + t) * DD + h * HD + e] = acc[e] * inv;
}

// ---------------- HMMA body GEMM: 64x64 tile, 4 warps, fp16 hi/lo 3-term ----------------
// C[M,N] = (LN?)(A)[M,K] @ B[N,K]^T (+bias/relu/residual); K % 128 == 0.
#define HG_GB 0                       // 256 floats (gamma/beta)
#define HG_ST 1024                    // 128 floats (mean/rstd)
#define HG_AH 1536
#define HG_AL (HG_AH + 17408)
#define HG_BH (HG_AL + 17408)
#define HG_BL (HG_BH + 17408)
#define HG_SMEM (HG_BL + 17408)       // 71168 bytes

template <int LNF>
__global__ void __launch_bounds__(128) hgemm_k(
    const float* __restrict__ A,
    const __half* __restrict__ Bh, const __half* __restrict__ Bl,
    const float* __restrict__ gam, const float* __restrict__ bet,
    const float* __restrict__ bias, const float* __restrict__ Rres,
    float* __restrict__ C, int M, int N, int K, int flags) {
    extern __shared__ __align__(16) char smem[];
    float* gb = (float*)(smem + HG_GB);
    float* mean_s = (float*)(smem + HG_ST);
    float* rstd_s = mean_s + 64;
    __half* Ah = (__half*)(smem + HG_AH);
    __half* Al = (__half*)(smem + HG_AL);
    __half* Bhs = (__half*)(smem + HG_BH);
    __half* Bls = (__half*)(smem + HG_BL);
    uint32_t sb = smem_u32(smem);

    int tid = threadIdx.x, wid = tid >> 5, lane = tid & 31;
    int bm0 = blockIdx.y * 64, bn0 = blockIdx.x * 64;
    int wm = (wid >> 1) * 32, wn = (wid & 1) * 32;
    int g = lane >> 2, t4 = lane & 3;

    if (LNF) {  // LN only used with K == 128
        gb[tid] = gam[tid];
        gb[128 + tid] = bet[tid];
        int rm = tid >> 1, hf = tid & 1;
        const float4* Ar = (const float4*)(A + (size_t)(bm0 + rm) * 128 + hf * 64);
        float s = 0.0f, s2 = 0.0f;
#pragma unroll
        for (int i2 = 0; i2 < 16; i2++) {
            float4 v = Ar[i2];
            s += v.x + v.y + v.z + v.w;
            s2 += v.x * v.x + v.y * v.y + v.z * v.z + v.w * v.w;
        }
        s += __shfl_xor_sync(0xffffffffu, s, 1);
        s2 += __shfl_xor_sync(0xffffffffu, s2, 1);
        if (hf == 0) {
            float mn = s * (1.0f / 128.0f);
            mean_s[rm] = mn;
            rstd_s[rm] = rsqrtf(s2 * (1.0f / 128.0f) - mn * mn + 1e-5f);
        }
        __syncthreads();
    }

    float acc[2][4][4];
#pragma unroll
    for (int i = 0; i < 2; i++)
#pragma unroll
        for (int j = 0; j < 4; j++)
#pragma unroll
            for (int q = 0; q < 4; q++) acc[i][j][q] = 0.0f;

    int lr = lane & 15, lk = lane >> 4;
    uint32_t aHb = sb + HG_AH + (uint32_t)((wm + lr) * 272 + lk * 16);
    uint32_t aLb = sb + HG_AL + (uint32_t)((wm + lr) * 272 + lk * 16);
    uint32_t bHb = sb + HG_BH + (uint32_t)((wn + lr) * 272 + lk * 16);
    uint32_t bLb = sb + HG_BL + (uint32_t)((wn + lr) * 272 + lk * 16);

    for (int kc = 0; kc < K; kc += 128) {
        if (kc) __syncthreads();
        // stage A (convert fp32 -> hi/lo, optional LN)
        for (int i = tid; i < 2048; i += 128) {
            int row = i >> 5;
            int kq = (i & 31) << 2;
            float4 v = *(const float4*)&A[(size_t)(bm0 + row) * K + kc + kq];
            float vv[4] = {v.x, v.y, v.z, v.w};
            if (LNF) {
                float mu = mean_s[row], rs = rstd_s[row];
#pragma unroll
                for (int j = 0; j < 4; j++)
                    vv[j] = (vv[j] - mu) * rs * gb[kq + j] + gb[128 + kq + j];
            }
#pragma unroll
            for (int j = 0; j < 4; j++) {
                __half hi = __float2half(vv[j]);
                Ah[row * 136 + kq + j] = hi;
                Al[row * 136 + kq + j] = __float2half(vv[j] - __half2float(hi));
            }
        }
        // stage B (raw fp16 hi/lo copy)
        {
            const uint4* bhp = (const uint4*)Bh;
            const uint4* blp = (const uint4*)Bl;
            int krow = K >> 3, kco = kc >> 3;
            for (int i = tid; i < 1024; i += 128) {
                int row = i >> 4, cb = i & 15;
                size_t gi = (size_t)(bn0 + row) * krow + kco + cb;
                *(uint4*)&Bhs[row * 136 + cb * 8] = bhp[gi];
                *(uint4*)&Bls[row * 136 + cb * 8] = blp[gi];
            }
        }
        __syncthreads();
        // mainloop: 8 k-steps of 16
#pragma unroll
        for (int ks = 0; ks < 8; ks++) {
            uint32_t off = (uint32_t)ks * 32;
            uint32_t ah0[4], ah1[4], al0[4], al1[4];
            uint32_t bh0[4], bh1[4], bl0[4], bl1[4];
            ldsm4(ah0, aHb + off); ldsm4(ah1, aHb + 16 * 272 + off);
            ldsm4(al0, aLb + off); ldsm4(al1, aLb + 16 * 272 + off);
            ldsm4(bh0, bHb + off); ldsm4(bh1, bHb + 16 * 272 + off);
            ldsm4(bl0, bLb + off); ldsm4(bl1, bLb + 16 * 272 + off);
#pragma unroll
            for (int i = 0; i < 2; i++) {
                const uint32_t* ahi = i ? ah1 : ah0;
                const uint32_t* alo = i ? al1 : al0;
#pragma unroll
                for (int j = 0; j < 4; j++) {
                    const uint32_t* bh = (j < 2) ? bh0 : bh1;
                    const uint32_t* bl = (j < 2) ? bl0 : bl1;
                    uint32_t b0h = bh[j & 1], b1h = bh[(j & 1) + 2];
                    uint32_t b0l = bl[j & 1], b1l = bl[(j & 1) + 2];
                    mma16816(acc[i][j], ahi, b0h, b1h);
                    mma16816(acc[i][j], alo, b0h, b1h);
                    mma16816(acc[i][j], ahi, b0l, b1l);
                }
            }
        }
    }

    // epilogue
#pragma unroll
    for (int i = 0; i < 2; i++) {
#pragma unroll
        for (int j = 0; j < 4; j++) {
            int col = bn0 + wn + j * 8 + 2 * t4;
            float bx = 0.0f, by = 0.0f;
            if (flags & 1) { bx = bias[col]; by = bias[col + 1]; }
            int r0 = bm0 + wm + i * 16 + g;
            float2 v0 = make_float2(acc[i][j][0] + bx, acc[i][j][1] + by);
            float2 v1 = make_float2(acc[i][j][2] + bx, acc[i][j][3] + by);
            if (flags & 2) {
                v0.x = fmaxf(v0.x, 0.f); v0.y = fmaxf(v0.y, 0.f);
                v1.x = fmaxf(v1.x, 0.f); v1.y = fmaxf(v1.y, 0.f);
            }
            if (flags & 4) {
                float2 r = *(const float2*)&Rres[(size_t)r0 * N + col];
                v0.x += r.x; v0.y += r.y;
                r = *(const float2*)&Rres[(size_t)(r0 + 8) * N + col];
                v1.x += r.x; v1.y += r.y;
            }
            *(float2*)&C[(size_t)r0 * N + col] = v0;
            *(float2*)&C[(size_t)(r0 + 8) * N + col] = v1;
        }
    }
}

// lm_w [128, V] -> transposed padded [NPAD, 128] fp16 (n-major)
__global__ void cvtb_k(const float* __restrict__ lm_w) {
    __shared__ float t[32][33];
    int n0 = blockIdx.x * 32, k0 = blockIdx.y * 32;
    int tx = threadIdx.x, ty = threadIdx.y;  // 32 x 8
    for (int i = ty; i < 32; i += 8) {
        int n = n0 + tx, k = k0 + i;
        t[i][tx] = (n < VV) ? lm_w[(size_t)k * VV + n] : 0.0f;
    }
    __syncthreads();
    for (int i = ty; i < 32; i += 8) {
        int n = n0 + i, k = k0 + tx;
        g_bh[(size_t)n * DD + k] = __float2half(t[tx][i]);
    }
}

// ---------------- HMMA LM head (pure fp16, ldmatrix) ----------------
#define PADH 136
#define ROWB (PADH * 2)                    // 272 bytes per row
#define AH_OFF 0
#define BH_OFF (128 * ROWB)                // 34816
#define BIAS_OFF (2 * 128 * ROWB)          // 69632
#define LM_SMEM (BIAS_OFF + 128 * 4)       // 70144

__global__ void __launch_bounds__(256, 3) lmhead_k(
    const float* __restrict__ bias, float* __restrict__ C) {
    extern __shared__ __align__(16) char smem[];
    uint32_t smem_base = smem_u32(smem);
    int tid = threadIdx.x;
    int wid = tid >> 5;
    int lane = tid & 31;
    int g = lane >> 2;
    int t4 = lane & 3;
    int bm0 = blockIdx.x * 128;
    int bn0 = blockIdx.y * 128;
    int wm = (wid >> 1) * 32;
    int wn = (wid & 1) * 64;

    {
        const uint4* gah = (const uint4*)g_ah;
        const uint4* gbh = (const uint4*)g_bh;
#pragma unroll
        for (int i = tid; i < 2048; i += 256) {
            int row = i >> 4, cb = i & 15;
            uint32_t so = (uint32_t)(row * ROWB + cb * 16);
            *(uint4*)(smem + AH_OFF + so) = gah[(size_t)(bm0 + row) * 16 + cb];
            *(uint4*)(smem + BH_OFF + so) = gbh[(size_t)(bn0 + row) * 16 + cb];
        }
        float* bs = (float*)(smem + BIAS_OFF);
        if (tid < 128) {
            int c = bn0 + tid;
            bs[tid] = (c < VV) ? bias[c] : 0.0f;
        }
    }
    __syncthreads();

    float acc[2][8][4];
#pragma unroll
    for (int i = 0; i < 2; i++)
#pragma unroll
        for (int j = 0; j < 8; j++)
#pragma unroll
            for (int q = 0; q < 4; q++) acc[i][j][q] = 0.0f;

    int lr = lane & 15;
    int lk = lane >> 4;
    uint32_t abase = smem_base + AH_OFF + (uint32_t)((wm + lr) * ROWB + lk * 16);
    uint32_t bbase[4];
#pragma unroll
    for (int jp = 0; jp < 4; jp++)
        bbase[jp] = smem_base + BH_OFF + (uint32_t)((wn + jp * 16 + lr) * ROWB + lk * 16);

#pragma unroll
    for (int ks = 0; ks < 8; ks++) {
        uint32_t off = (uint32_t)ks * 32;
        uint32_t a0[4], a1[4];
        ldsm4(a0, abase + off);
        ldsm4(a1, abase + (uint32_t)(16 * ROWB) + off);
#pragma unroll
        for (int jp = 0; jp < 4; jp++) {
            uint32_t r[4];
            ldsm4(r, bbase[jp] + off);
            mma16816(acc[0][2 * jp],     a0, r[0], r[2]);
            mma16816(acc[0][2 * jp + 1], a0, r[1], r[3]);
            mma16816(acc[1][2 * jp],     a1, r[0], r[2]);
            mma16816(acc[1][2 * jp + 1], a1, r[1], r[3]);
        }
    }

    const float* bs = (const float*)(smem + BIAS_OFF);
    bool full = (bn0 + 128 <= VV);
#pragma unroll
    for (int i = 0; i < 2; i++) {
#pragma unroll
        for (int half = 0; half < 2; half++) {
            int gr = bm0 + wm + i * 16 + half * 8 + g;
            float* crow = C + (size_t)gr * VV + bn0;
            float s = 0.0f;
            if (full) {
#pragma unroll
                for (int j = 0; j < 8; j++) {
                    int lc = wn + j * 8 + 2 * t4;
                    float v0 = acc[i][j][half * 2 + 0] + bs[lc];
                    float v1 = acc[i][j][half * 2 + 1] + bs[lc + 1];
                    crow[lc] = v0;
                    crow[lc + 1] = v1;
                    s += __expf(v0) + __expf(v1);
                }
            } else {
#pragma unroll
                for (int j = 0; j < 8; j++) {
                    int lc = wn + j * 8 + 2 * t4;
                    int col = bn0 + lc;
                    float v0 = acc[i][j][half * 2 + 0] + bs[lc];
                    float v1 = acc[i][j][half * 2 + 1] + bs[lc + 1];
                    if (col < VV) { crow[lc] = v0; s += __expf(v0); }
                    if (col + 1 < VV) { crow[lc + 1] = v1; s += __expf(v1); }
                }
            }
            s += __shfl_xor_sync(0xffffffffu, s, 1);
            s += __shfl_xor_sync(0xffffffffu, s, 2);
            if (t4 == 0)
                g_part[(size_t)gr * NPART + blockIdx.y * 2 + (wid & 1)] = s;
        }
    }
}

// ---------------- NLL from partials ----------------
__global__ void nllred_k(const float* __restrict__ logits, const int* __restrict__ tgt) {
    int r = blockIdx.x;
    int tid = threadIdx.x;  // 128
    float s = 0.0f;
    for (int c = tid; c < NPART; c += 128) s += g_part[(size_t)r * NPART + c];
    __shared__ float red[4];
#pragma unroll
    for (int o = 16; o > 0; o >>= 1) s += __shfl_xor_sync(0xffffffffu, s, o);
    if ((tid & 31) == 0) red[tid >> 5] = s;
    __syncthreads();
    if (tid == 0) {
        float tot = red[0] + red[1] + red[2] + red[3];
        g_nll[r] = logf(tot) - logits[(size_t)r * VV + tgt[r]];
    }
}

__global__ void loss_k(float* __restrict__ out) {
    __shared__ float accs[256];
    float s = 0.0f;
    for (int i = threadIdx.x; i < BT; i += 256) s += g_nll[i];
    accs[threadIdx.x] = s;
    __syncthreads();
    for (int o = 128; o > 0; o >>= 1) {
        if (threadIdx.x < o) accs[threadIdx.x] += accs[threadIdx.x + o];
        __syncthreads();
    }
    if (threadIdx.x == 0) out[0] = accs[0] * (1.0f / BT);
}

// ---------------- host launcher ----------------
static void launch_hgemm(const float* A, const __half* Bh, const __half* Bl,
                         const float* gam, const float* bet,
                         const float* bias, const float* res, float* C,
                         int M, int N, int K, int flags, bool ln) {
    dim3 grid(N / 64, M / 64);
    if (ln)
        hgemm_k<1><<<grid, 128, HG_SMEM>>>(A, Bh, Bl, gam, bet, bias, res, C, M, N, K, flags);
    else
        hgemm_k<0><<<grid, 128, HG_SMEM>>>(A, Bh, Bl, gam, bet, bias, res, C, M, N, K, flags);
}

extern "C" void kernel_launch(void* const* d_in, const int* in_sizes, int n_in,
                              void* d_out, int out_size) {
    const int* idx       = (const int*)d_in[0];
    const int* targets   = (const int*)d_in[1];
    const float* tok_emb = (const float*)d_in[2];
    const float* pos_emb = (const float*)d_in[3];
    const float* wq      = (const float*)d_in[4];
    const float* wk      = (const float*)d_in[5];
    const float* wv      = (const float*)d_in[6];
    const float* wproj   = (const float*)d_in[7];
    const float* bproj   = (const float*)d_in[8];
    const float* w1      = (const float*)d_in[9];
    const float* b1      = (const float*)d_in[10];
    const float* w2      = (const float*)d_in[11];
    const float* b2      = (const float*)d_in[12];
    const float* ln1_g   = (const float*)d_in[13];
    const float* ln1_b   = (const float*)d_in[14];
    const float* ln2_g   = (const float*)d_in[15];
    const float* ln2_b   = (const float*)d_in[16];
    const float* lnf_g   = (const float*)d_in[17];
    const float* lnf_b   = (const float*)d_in[18];
    const float* lm_w    = (const float*)d_in[19];
    const float* lm_b    = (const float*)d_in[20];
    float* out = (float*)d_out;

    float *px, *pqkv, *po, *pm;
    __half *pwqkvh, *pwqkvl, *pwph, *pwpl, *pw1h, *pw1l, *pw2h, *pw2l;
    cudaGetSymbolAddress((void**)&px, g_x);
    cudaGetSymbolAddress((void**)&pqkv, g_qkv);
    cudaGetSymbolAddress((void**)&po, g_o);
    cudaGetSymbolAddress((void**)&pm, g_m);
    cudaGetSymbolAddress((void**)&pwqkvh, g_wqkvh);
    cudaGetSymbolAddress((void**)&pwqkvl, g_wqkvl);
    cudaGetSymbolAddress((void**)&pwph, g_wph);
    cudaGetSymbolAddress((void**)&pwpl, g_wpl);
    cudaGetSymbolAddress((void**)&pw1h, g_w1h);
    cudaGetSymbolAddress((void**)&pw1l, g_w1l);
    cudaGetSymbolAddress((void**)&pw2h, g_w2h);
    cudaGetSymbolAddress((void**)&pw2l, g_w2l);

    cudaFuncSetAttribute(lmhead_k, cudaFuncAttributeMaxDynamicSharedMemorySize, LM_SMEM);
    cudaFuncSetAttribute(hgemm_k<0>, cudaFuncAttributeMaxDynamicSharedMemorySize, HG_SMEM);
    cudaFuncSetAttribute(hgemm_k<1>, cudaFuncAttributeMaxDynamicSharedMemorySize, HG_SMEM);

    embed_k<<<BT, DD>>>(idx, tok_emb, pos_emb);
    cvtwqkv_k<<<(LL * 384 * DD + 255) / 256, 256>>>(wq, wk, wv);
    cvtw_k<<<dim3(DD / 32, DD / 32, LL), dim3(32, 8)>>>(wproj, pwph, pwpl, DD, DD);
    cvtw_k<<<dim3(DFF / 32, DD / 32, LL), dim3(32, 8)>>>(w1, pw1h, pw1l, DD, DFF);
    cvtw_k<<<dim3(DD / 32, DFF / 32, LL), dim3(32, 8)>>>(w2, pw2h, pw2l, DFF, DD);
    cvtb_k<<<dim3(NPAD / 32, 4), dim3(32, 8)>>>(lm_w);

    for (int l = 0; l < LL; l++) {
        // LN1 + QKV
        launch_hgemm(px, pwqkvh + (size_t)l * 384 * DD, pwqkvl + (size_t)l * 384 * DD,
                     ln1_g + l * DD, ln1_b + l * DD, nullptr, nullptr,
                     pqkv, BT, 384, DD, 0, true);
        attn_k<<<BB * HH, TT>>>();
        // proj + bias + residual
        launch_hgemm(po, pwph + (size_t)l * DD * DD, pwpl + (size_t)l * DD * DD,
                     nullptr, nullptr, bproj + l * DD, px,
                     px, BT, DD, DD, 1 | 4, false);
        // LN2 + MLP1 (bias+relu)
        launch_hgemm(px, pw1h + (size_t)l * DFF * DD, pw1l + (size_t)l * DFF * DD,
                     ln2_g + l * DD, ln2_b + l * DD, b1 + l * DFF, nullptr,
                     pm, BT, DFF, DD, 1 | 2, true);
        // MLP2 + bias + residual
        launch_hgemm(pm, pw2h + (size_t)l * DD * DFF, pw2l + (size_t)l * DD * DFF,
                     nullptr, nullptr, b2 + l * DD, px,
                     px, BT, DD, DFF, 1 | 4, false);
    }

    lncvt_k<<<BT, DD>>>(px, lnf_g, lnf_b);

    dim3 lgrid(BT / 128, NBLK);
    lmhead_k<<<lgrid, 256, LM_SMEM>>>(lm_b, out);

    nllred_k<<<BT, 128>>>(out, targets);
    if (out_size > BT * VV) {
        loss_k<<<1, 256>>>(out + (size_t)BT * VV);
    }
}

// round 14
// speedup vs baseline: 3.8767x; 1.1190x over previous
#include <cuda_runtime.h>
#include <cuda_bf16.h>
#include <cuda_fp16.h>
#include <math.h>
#include <stdint.h>

#define BB 32
#define TT 128
#define DD 128
#define HH 8
#define HD 16
#define LL 4
#define VV 50257
#define BT (BB * TT)       // 4096
#define DFF (4 * DD)       // 512
#define NBLK 393                 // ceil(VV / 128)
#define NPAD (NBLK * 128)        // 50304

// ---------------- scratch ----------------
__device__ float g_x[BT * DD];
__device__ float g_qkv[BT * 384];
__device__ float g_o[BT * DD];
__device__ float g_m[BT * DFF];
__device__ float g_part[(size_t)BT * NBLK];
__device__ float g_nll[BT];
__device__ __half g_ah[BT * DD];
__device__ __half g_bh[(size_t)NPAD * DD];
// body weights, n-major [N][K] fp16 hi/lo
__device__ __half g_wqkvh[LL * 384 * DD], g_wqkvl[LL * 384 * DD];
__device__ __half g_wph[LL * DD * DD],   g_wpl[LL * DD * DD];
__device__ __half g_w1h[LL * DFF * DD],  g_w1l[LL * DFF * DD];
__device__ __half g_w2h[LL * DD * DFF],  g_w2l[LL * DD * DFF];

// ---------------- helpers ----------------
__device__ __forceinline__ uint32_t smem_u32(const void* p) {
    uint32_t a;
    asm("{ .reg .u64 t; cvta.to.shared.u64 t, %1; cvt.u32.u64 %0, t; }" : "=r"(a) : "l"(p));
    return a;
}
__device__ __forceinline__ void mma16816(float* c, const uint32_t* a,
                                         uint32_t b0, uint32_t b1) {
    asm volatile(
        "mma.sync.aligned.m16n8k16.row.col.f32.f16.f16.f32 "
        "{%0,%1,%2,%3}, {%4,%5,%6,%7}, {%8,%9}, {%0,%1,%2,%3};"
        : "+f"(c[0]), "+f"(c[1]), "+f"(c[2]), "+f"(c[3])
        : "r"(a[0]), "r"(a[1]), "r"(a[2]), "r"(a[3]), "r"(b0), "r"(b1));
}
__device__ __forceinline__ void ldsm4(uint32_t* r, uint32_t addr) {
    asm volatile("ldmatrix.sync.aligned.m8n8.x4.shared.b16 {%0,%1,%2,%3}, [%4];"
                 : "=r"(r[0]), "=r"(r[1]), "=r"(r[2]), "=r"(r[3]) : "r"(addr));
}
__device__ __forceinline__ void stcs(float* p, float v) {
    asm volatile("st.global.cs.f32 [%0], %1;" :: "l"(p), "f"(v) : "memory");
}

// ---------------- embedding ----------------
__global__ void embed_k(const int* __restrict__ idx,
                        const float* __restrict__ tok,
                        const float* __restrict__ pos) {
    int m = blockIdx.x;
    int d = threadIdx.x;
    int t = m & (TT - 1);
    g_x[m * DD + d] = tok[(size_t)idx[m] * DD + d] + pos[t * DD + d];
}

// ---------------- qkv weights [L,H,D,HD] -> n-major [L][384][128] fp16 hi/lo ----------------
__global__ void cvtwqkv_k(const float* __restrict__ wq,
                          const float* __restrict__ wk,
                          const float* __restrict__ wv) {
    int o = blockIdx.x * 256 + threadIdx.x;
    if (o >= LL * 384 * DD) return;
    int l = o / (384 * DD);
    int rem = o % (384 * DD);
    int n = rem >> 7, d = rem & 127;
    int which = n >> 7;
    int nn = n & 127;
    int h = nn >> 4, e = nn & 15;
    const float* W = (which == 0) ? wq : (which == 1) ? wk : wv;
    float x = W[(((size_t)l * HH + h) * DD + d) * HD + e];
    __half hi = __float2half(x);
    g_wqkvh[o] = hi;
    g_wqkvl[o] = __float2half(x - __half2float(hi));
}

// ---------------- generic weight transpose-convert: W[l][K][N] -> [l][N][K] hi/lo ----------------
__global__ void cvtw_k(const float* __restrict__ W, __half* __restrict__ oh,
                       __half* __restrict__ ol, int K, int N) {
    __shared__ float t[32][33];
    int l = blockIdx.z;
    const float* Wl = W + (size_t)l * K * N;
    __half* ohl = oh + (size_t)l * N * K;
    __half* oll = ol + (size_t)l * N * K;
    int n0 = blockIdx.x * 32, k0 = blockIdx.y * 32;
    int tx = threadIdx.x, ty = threadIdx.y;  // 32 x 8
    for (int i = ty; i < 32; i += 8)
        t[i][tx] = Wl[(size_t)(k0 + i) * N + n0 + tx];
    __syncthreads();
    for (int i = ty; i < 32; i += 8) {
        int n = n0 + i, k = k0 + tx;
        float x = t[tx][i];
        __half hi = __float2half(x);
        ohl[(size_t)n * K + k] = hi;
        oll[(size_t)n * K + k] = __float2half(x - __half2float(hi));
    }
}

// ---------------- final LN fused with fp16 convert ----------------
__global__ void lncvt_k(const float* __restrict__ in,
                        const float* __restrict__ gam, const float* __restrict__ bet) {
    __shared__ float red[4];
    int m = blockIdx.x, d = threadIdx.x;
    int i = m * DD + d;
    float x = in[i];
    float s = x;
#pragma unroll
    for (int o = 16; o > 0; o >>= 1) s += __shfl_xor_sync(0xffffffffu, s, o);
    if ((d & 31) == 0) red[d >> 5] = s;
    __syncthreads();
    float mean = (red[0] + red[1] + red[2] + red[3]) * (1.0f / DD);
    __syncthreads();
    float c = x - mean;
    float cs = c * c;
#pragma unroll
    for (int o = 16; o > 0; o >>= 1) cs += __shfl_xor_sync(0xffffffffu, cs, o);
    if ((d & 31) == 0) red[d >> 5] = cs;
    __syncthreads();
    float var = (red[0] + red[1] + red[2] + red[3]) * (1.0f / DD);
    float y = c * rsqrtf(var + 1e-5f) * gam[d] + bet[d];
    g_ah[i] = __float2half(y);
}

// ---------------- attention ----------------
__global__ void attn_k() {
    int b = blockIdx.x / HH;
    int h = blockIdx.x % HH;
    int t = threadIdx.x;
    __shared__ float ks[TT][HD];
    __shared__ float vs[TT][HD];
    const float* rowp = g_qkv + (size_t)(b * TT + t) * 384 + h * HD;
#pragma unroll
    for (int e = 0; e < HD; e++) {
        ks[t][e] = rowp[128 + e];
        vs[t][e] = rowp[256 + e];
    }
    __syncthreads();
    float q[HD];
#pragma unroll
    for (int e = 0; e < HD; e++) q[e] = rowp[e];

    const float scale = 0.08838834764831845f;  // 1/sqrt(128)
    float mrun = -1e30f, lrun = 0.0f;
    float acc[HD];
#pragma unroll
    for (int e = 0; e < HD; e++) acc[e] = 0.0f;
    for (int s = 0; s <= t; s++) {
        float d = 0.0f;
#pragma unroll
        for (int e = 0; e < HD; e++) d += q[e] * ks[s][e];
        d *= scale;
        float mn = fmaxf(mrun, d);
        float corr = __expf(mrun - mn);
        float p = __expf(d - mn);
        lrun = lrun * corr + p;
#pragma unroll
        for (int e = 0; e < HD; e++) acc[e] = acc[e] * corr + p * vs[s][e];
        mrun = mn;
    }
    float inv = 1.0f / lrun;
#pragma unroll
    for (int e = 0; e < HD; e++)
        g_o[(size_t)(b * TT + t) * DD + h * HD + e] = acc[e] * inv;
}

// ---------------- HMMA body GEMM: 64x64 tile, 4 warps, fp16 hi/lo 3-term ----------------
#define HG_GB 0
#define HG_ST 1024
#define HG_AH 1536
#define HG_AL (HG_AH + 17408)
#define HG_BH (HG_AL + 17408)
#define HG_BL (HG_BH + 17408)
#define HG_SMEM (HG_BL + 17408)       // 71168 bytes

template <int LNF>
__global__ void __launch_bounds__(128) hgemm_k(
    const float* __restrict__ A,
    const __half* __restrict__ Bh, const __half* __restrict__ Bl,
    const float* __restrict__ gam, const float* __restrict__ bet,
    const float* __restrict__ bias, const float* __restrict__ Rres,
    float* __restrict__ C, int M, int N, int K, int flags) {
    extern __shared__ __align__(16) char smem[];
    float* gb = (float*)(smem + HG_GB);
    float* mean_s = (float*)(smem + HG_ST);
    float* rstd_s = mean_s + 64;
    __half* Ah = (__half*)(smem + HG_AH);
    __half* Al = (__half*)(smem + HG_AL);
    __half* Bhs = (__half*)(smem + HG_BH);
    __half* Bls = (__half*)(smem + HG_BL);
    uint32_t sb = smem_u32(smem);

    int tid = threadIdx.x, wid = tid >> 5, lane = tid & 31;
    int bm0 = blockIdx.y * 64, bn0 = blockIdx.x * 64;
    int wm = (wid >> 1) * 32, wn = (wid & 1) * 32;
    int g = lane >> 2, t4 = lane & 3;

    if (LNF) {
        gb[tid] = gam[tid];
        gb[128 + tid] = bet[tid];
        int rm = tid >> 1, hf = tid & 1;
        const float4* Ar = (const float4*)(A + (size_t)(bm0 + rm) * 128 + hf * 64);
        float s = 0.0f, s2 = 0.0f;
#pragma unroll
        for (int i2 = 0; i2 < 16; i2++) {
            float4 v = Ar[i2];
            s += v.x + v.y + v.z + v.w;
            s2 += v.x * v.x + v.y * v.y + v.z * v.z + v.w * v.w;
        }
        s += __shfl_xor_sync(0xffffffffu, s, 1);
        s2 += __shfl_xor_sync(0xffffffffu, s2, 1);
        if (hf == 0) {
            float mn = s * (1.0f / 128.0f);
            mean_s[rm] = mn;
            rstd_s[rm] = rsqrtf(s2 * (1.0f / 128.0f) - mn * mn + 1e-5f);
        }
        __syncthreads();
    }

    float acc[2][4][4];
#pragma unroll
    for (int i = 0; i < 2; i++)
#pragma unroll
        for (int j = 0; j < 4; j++)
#pragma unroll
            for (int q = 0; q < 4; q++) acc[i][j][q] = 0.0f;

    int lr = lane & 15, lk = lane >> 4;
    uint32_t aHb = sb + HG_AH + (uint32_t)((wm + lr) * 272 + lk * 16);
    uint32_t aLb = sb + HG_AL + (uint32_t)((wm + lr) * 272 + lk * 16);
    uint32_t bHb = sb + HG_BH + (uint32_t)((wn + lr) * 272 + lk * 16);
    uint32_t bLb = sb + HG_BL + (uint32_t)((wn + lr) * 272 + lk * 16);

    for (int kc = 0; kc < K; kc += 128) {
        if (kc) __syncthreads();
        for (int i = tid; i < 2048; i += 128) {
            int row = i >> 5;
            int kq = (i & 31) << 2;
            float4 v = *(const float4*)&A[(size_t)(bm0 + row) * K + kc + kq];
            float vv[4] = {v.x, v.y, v.z, v.w};
            if (LNF) {
                float mu = mean_s[row], rs = rstd_s[row];
#pragma unroll
                for (int j = 0; j < 4; j++)
                    vv[j] = (vv[j] - mu) * rs * gb[kq + j] + gb[128 + kq + j];
            }
#pragma unroll
            for (int j = 0; j < 4; j++) {
                __half hi = __float2half(vv[j]);
                Ah[row * 136 + kq + j] = hi;
                Al[row * 136 + kq + j] = __float2half(vv[j] - __half2float(hi));
            }
        }
        {
            const uint4* bhp = (const uint4*)Bh;
            const uint4* blp = (const uint4*)Bl;
            int krow = K >> 3, kco = kc >> 3;
            for (int i = tid; i < 1024; i += 128) {
                int row = i >> 4, cb = i & 15;
                size_t gi = (size_t)(bn0 + row) * krow + kco + cb;
                *(uint4*)&Bhs[row * 136 + cb * 8] = bhp[gi];
                *(uint4*)&Bls[row * 136 + cb * 8] = blp[gi];
            }
        }
        __syncthreads();
#pragma unroll
        for (int ks = 0; ks < 8; ks++) {
            uint32_t off = (uint32_t)ks * 32;
            uint32_t ah0[4], ah1[4], al0[4], al1[4];
            uint32_t bh0[4], bh1[4], bl0[4], bl1[4];
            ldsm4(ah0, aHb + off); ldsm4(ah1, aHb + 16 * 272 + off);
            ldsm4(al0, aLb + off); ldsm4(al1, aLb + 16 * 272 + off);
            ldsm4(bh0, bHb + off); ldsm4(bh1, bHb + 16 * 272 + off);
            ldsm4(bl0, bLb + off); ldsm4(bl1, bLb + 16 * 272 + off);
#pragma unroll
            for (int i = 0; i < 2; i++) {
                const uint32_t* ahi = i ? ah1 : ah0;
                const uint32_t* alo = i ? al1 : al0;
#pragma unroll
                for (int j = 0; j < 4; j++) {
                    const uint32_t* bh = (j < 2) ? bh0 : bh1;
                    const uint32_t* bl = (j < 2) ? bl0 : bl1;
                    uint32_t b0h = bh[j & 1], b1h = bh[(j & 1) + 2];
                    uint32_t b0l = bl[j & 1], b1l = bl[(j & 1) + 2];
                    mma16816(acc[i][j], ahi, b0h, b1h);
                    mma16816(acc[i][j], alo, b0h, b1h);
                    mma16816(acc[i][j], ahi, b0l, b1l);
                }
            }
        }
    }

#pragma unroll
    for (int i = 0; i < 2; i++) {
#pragma unroll
        for (int j = 0; j < 4; j++) {
            int col = bn0 + wn + j * 8 + 2 * t4;
            float bx = 0.0f, by = 0.0f;
            if (flags & 1) { bx = bias[col]; by = bias[col + 1]; }
            int r0 = bm0 + wm + i * 16 + g;
            float2 v0 = make_float2(acc[i][j][0] + bx, acc[i][j][1] + by);
            float2 v1 = make_float2(acc[i][j][2] + bx, acc[i][j][3] + by);
            if (flags & 2) {
                v0.x = fmaxf(v0.x, 0.f); v0.y = fmaxf(v0.y, 0.f);
                v1.x = fmaxf(v1.x, 0.f); v1.y = fmaxf(v1.y, 0.f);
            }
            if (flags & 4) {
                float2 r = *(const float2*)&Rres[(size_t)r0 * N + col];
                v0.x += r.x; v0.y += r.y;
                r = *(const float2*)&Rres[(size_t)(r0 + 8) * N + col];
                v1.x += r.x; v1.y += r.y;
            }
            *(float2*)&C[(size_t)r0 * N + col] = v0;
            *(float2*)&C[(size_t)(r0 + 8) * N + col] = v1;
        }
    }
}

// lm_w [128, V] -> transposed padded [NPAD, 128] fp16 (n-major)
__global__ void cvtb_k(const float* __restrict__ lm_w) {
    __shared__ float t[32][33];
    int n0 = blockIdx.x * 32, k0 = blockIdx.y * 32;
    int tx = threadIdx.x, ty = threadIdx.y;  // 32 x 8
    for (int i = ty; i < 32; i += 8) {
        int n = n0 + tx, k = k0 + i;
        t[i][tx] = (n < VV) ? lm_w[(size_t)k * VV + n] : 0.0f;
    }
    __syncthreads();
    for (int i = ty; i < 32; i += 8) {
        int n = n0 + i, k = k0 + tx;
        g_bh[(size_t)n * DD + k] = __float2half(t[tx][i]);
    }
}

// ---------------- HMMA LM head (pure fp16, ldmatrix, staged coalesced epilogue) ----------------
#define PADH 136
#define ROWB (PADH * 2)                    // 272 bytes per row
#define AH_OFF 0
#define BH_OFF (128 * ROWB)                // 34816
#define BIAS_OFF (2 * 128 * ROWB)          // 69632
#define LM_SMEM (BIAS_OFF + 128 * 4)       // 70144

__global__ void __launch_bounds__(256, 3) lmhead_k(
    const float* __restrict__ bias, float* __restrict__ C) {
    extern __shared__ __align__(16) char smem[];
    uint32_t smem_base = smem_u32(smem);
    int tid = threadIdx.x;
    int wid = tid >> 5;
    int lane = tid & 31;
    int g = lane >> 2;
    int t4 = lane & 3;
    int bm0 = blockIdx.x * 128;
    int bn0 = blockIdx.y * 128;
    int wm = (wid >> 1) * 32;
    int wn = (wid & 1) * 64;

    {
        const uint4* gah = (const uint4*)g_ah;
        const uint4* gbh = (const uint4*)g_bh;
#pragma unroll
        for (int i = tid; i < 2048; i += 256) {
            int row = i >> 4, cb = i & 15;
            uint32_t so = (uint32_t)(row * ROWB + cb * 16);
            *(uint4*)(smem + AH_OFF + so) = gah[(size_t)(bm0 + row) * 16 + cb];
            *(uint4*)(smem + BH_OFF + so) = gbh[(size_t)(bn0 + row) * 16 + cb];
        }
        float* bs = (float*)(smem + BIAS_OFF);
        if (tid < 128) {
            int c = bn0 + tid;
            bs[tid] = (c < VV) ? bias[c] : 0.0f;
        }
    }
    __syncthreads();

    float acc[2][8][4];
#pragma unroll
    for (int i = 0; i < 2; i++)
#pragma unroll
        for (int j = 0; j < 8; j++)
#pragma unroll
            for (int q = 0; q < 4; q++) acc[i][j][q] = 0.0f;

    int lr = lane & 15;
    int lk = lane >> 4;
    uint32_t abase = smem_base + AH_OFF + (uint32_t)((wm + lr) * ROWB + lk * 16);
    uint32_t bbase[4];
#pragma unroll
    for (int jp = 0; jp < 4; jp++)
        bbase[jp] = smem_base + BH_OFF + (uint32_t)((wn + jp * 16 + lr) * ROWB + lk * 16);

#pragma unroll
    for (int ks = 0; ks < 8; ks++) {
        uint32_t off = (uint32_t)ks * 32;
        uint32_t a0[4], a1[4];
        ldsm4(a0, abase + off);
        ldsm4(a1, abase + (uint32_t)(16 * ROWB) + off);
#pragma unroll
        for (int jp = 0; jp < 4; jp++) {
            uint32_t r[4];
            ldsm4(r, bbase[jp] + off);
            mma16816(acc[0][2 * jp],     a0, r[0], r[2]);
            mma16816(acc[0][2 * jp + 1], a0, r[1], r[3]);
            mma16816(acc[1][2 * jp],     a1, r[0], r[2]);
            mma16816(acc[1][2 * jp + 1], a1, r[1], r[3]);
        }
    }

    // ---- stage accumulators to smem (A/B tiles dead; bias region preserved) ----
    __syncthreads();
    float* stage = (float*)smem;  // 128 rows x 136 floats = 69632 bytes
#pragma unroll
    for (int i = 0; i < 2; i++) {
#pragma unroll
        for (int half = 0; half < 2; half++) {
            int r = wm + i * 16 + half * 8 + g;
#pragma unroll
            for (int j = 0; j < 8; j++) {
                int c = wn + j * 8 + 2 * t4;
                *(float2*)&stage[r * 136 + c] =
                    make_float2(acc[i][j][half * 2], acc[i][j][half * 2 + 1]);
            }
        }
    }
    __syncthreads();

    // ---- drain: coalesced per-row streaming stores + fused sum(exp) ----
    const float* bs = (const float*)(smem + BIAS_OFF);
    for (int rr = 0; rr < 16; rr++) {
        int r = wid * 16 + rr;
        int grow = bm0 + r;
        float* crow = C + (size_t)grow * VV + bn0;
        float s = 0.0f;
#pragma unroll
        for (int p = 0; p < 4; p++) {
            int col = p * 32 + lane;
            float v = stage[r * 136 + col] + bs[col];
            if (bn0 + col < VV) {
                stcs(crow + col, v);
                s += __expf(v);
            }
        }
#pragma unroll
        for (int o = 16; o > 0; o >>= 1) s += __shfl_xor_sync(0xffffffffu, s, o);
        if (lane == 0) g_part[(size_t)grow * NBLK + blockIdx.y] = s;
    }
}

// ---------------- NLL from partials ----------------
__global__ void nllred_k(const float* __restrict__ logits, const int* __restrict__ tgt) {
    int r = blockIdx.x;
    int tid = threadIdx.x;  // 128
    float s = 0.0f;
    for (int c = tid; c < NBLK; c += 128) s += g_part[(size_t)r * NBLK + c];
    __shared__ float red[4];
#pragma unroll
    for (int o = 16; o > 0; o >>= 1) s += __shfl_xor_sync(0xffffffffu, s, o);
    if ((tid & 31) == 0) red[tid >> 5] = s;
    __syncthreads();
    if (tid == 0) {
        float tot = red[0] + red[1] + red[2] + red[3];
        g_nll[r] = logf(tot) - logits[(size_t)r * VV + tgt[r]];
    }
}

__global__ void loss_k(float* __restrict__ out) {
    __shared__ float accs[256];
    float s = 0.0f;
    for (int i = threadIdx.x; i < BT; i += 256) s += g_nll[i];
    accs[threadIdx.x] = s;
    __syncthreads();
    for (int o = 128; o > 0; o >>= 1) {
        if (threadIdx.x < o) accs[threadIdx.x] += accs[threadIdx.x + o];
        __syncthreads();
    }
    if (threadIdx.x == 0) out[0] = accs[0] * (1.0f / BT);
}

// ---------------- host launcher ----------------
static void launch_hgemm(const float* A, const __half* Bh, const __half* Bl,
                         const float* gam, const float* bet,
                         const float* bias, const float* res, float* C,
                         int M, int N, int K, int flags, bool ln) {
    dim3 grid(N / 64, M / 64);
    if (ln)
        hgemm_k<1><<<grid, 128, HG_SMEM>>>(A, Bh, Bl, gam, bet, bias, res, C, M, N, K, flags);
    else
        hgemm_k<0><<<grid, 128, HG_SMEM>>>(A, Bh, Bl, gam, bet, bias, res, C, M, N, K, flags);
}

extern "C" void kernel_launch(void* const* d_in, const int* in_sizes, int n_in,
                              void* d_out, int out_size) {
    const int* idx       = (const int*)d_in[0];
    const int* targets   = (const int*)d_in[1];
    const float* tok_emb = (const float*)d_in[2];
    const float* pos_emb = (const float*)d_in[3];
    const float* wq      = (const float*)d_in[4];
    const float* wk      = (const float*)d_in[5];
    const float* wv      = (const float*)d_in[6];
    const float* wproj   = (const float*)d_in[7];
    const float* bproj   = (const float*)d_in[8];
    const float* w1      = (const float*)d_in[9];
    const float* b1      = (const float*)d_in[10];
    const float* w2      = (const float*)d_in[11];
    const float* b2      = (const float*)d_in[12];
    const float* ln1_g   = (const float*)d_in[13];
    const float* ln1_b   = (const float*)d_in[14];
    const float* ln2_g   = (const float*)d_in[15];
    const float* ln2_b   = (const float*)d_in[16];
    const float* lnf_g   = (const float*)d_in[17];
    const float* lnf_b   = (const float*)d_in[18];
    const float* lm_w    = (const float*)d_in[19];
    const float* lm_b    = (const float*)d_in[20];
    float* out = (float*)d_out;

    float *px, *pqkv, *po, *pm;
    __half *pwqkvh, *pwqkvl, *pwph, *pwpl, *pw1h, *pw1l, *pw2h, *pw2l;
    cudaGetSymbolAddress((void**)&px, g_x);
    cudaGetSymbolAddress((void**)&pqkv, g_qkv);
    cudaGetSymbolAddress((void**)&po, g_o);
    cudaGetSymbolAddress((void**)&pm, g_m);
    cudaGetSymbolAddress((void**)&pwqkvh, g_wqkvh);
    cudaGetSymbolAddress((void**)&pwqkvl, g_wqkvl);
    cudaGetSymbolAddress((void**)&pwph, g_wph);
    cudaGetSymbolAddress((void**)&pwpl, g_wpl);
    cudaGetSymbolAddress((void**)&pw1h, g_w1h);
    cudaGetSymbolAddress((void**)&pw1l, g_w1l);
    cudaGetSymbolAddress((void**)&pw2h, g_w2h);
    cudaGetSymbolAddress((void**)&pw2l, g_w2l);

    cudaFuncSetAttribute(lmhead_k, cudaFuncAttributeMaxDynamicSharedMemorySize, LM_SMEM);
    cudaFuncSetAttribute(hgemm_k<0>, cudaFuncAttributeMaxDynamicSharedMemorySize, HG_SMEM);
    cudaFuncSetAttribute(hgemm_k<1>, cudaFuncAttributeMaxDynamicSharedMemorySize, HG_SMEM);

    embed_k<<<BT, DD>>>(idx, tok_emb, pos_emb);
    cvtwqkv_k<<<(LL * 384 * DD + 255) / 256, 256>>>(wq, wk, wv);
    cvtw_k<<<dim3(DD / 32, DD / 32, LL), dim3(32, 8)>>>(wproj, pwph, pwpl, DD, DD);
    cvtw_k<<<dim3(DFF / 32, DD / 32, LL), dim3(32, 8)>>>(w1, pw1h, pw1l, DD, DFF);
    cvtw_k<<<dim3(DD / 32, DFF / 32, LL), dim3(32, 8)>>>(w2, pw2h, pw2l, DFF, DD);
    cvtb_k<<<dim3(NPAD / 32, 4), dim3(32, 8)>>>(lm_w);

    for (int l = 0; l < LL; l++) {
        launch_hgemm(px, pwqkvh + (size_t)l * 384 * DD, pwqkvl + (size_t)l * 384 * DD,
                     ln1_g + l * DD, ln1_b + l * DD, nullptr, nullptr,
                     pqkv, BT, 384, DD, 0, true);
        attn_k<<<BB * HH, TT>>>();
        launch_hgemm(po, pwph + (size_t)l * DD * DD, pwpl + (size_t)l * DD * DD,
                     nullptr, nullptr, bproj + l * DD, px,
                     px, BT, DD, DD, 1 | 4, false);
        launch_hgemm(px, pw1h + (size_t)l * DFF * DD, pw1l + (size_t)l * DFF * DD,
                     ln2_g + l * DD, ln2_b + l * DD, b1 + l * DFF, nullptr,
                     pm, BT, DFF, DD, 1 | 2, true);
        launch_hgemm(pm, pw2h + (size_t)l * DD * DFF, pw2l + (size_t)l * DD * DFF,
                     nullptr, nullptr, b2 + l * DD, px,
                     px, BT, DD, DFF, 1 | 4, false);
    }

    lncvt_k<<<BT, DD>>>(px, lnf_g, lnf_b);

    dim3 lgrid(BT / 128, NBLK);
    lmhead_k<<<lgrid, 256, LM_SMEM>>>(lm_b, out);

    nllred_k<<<BT, 128>>>(out, targets);
    if (out_size > BT * VV) {
        loss_k<<<1, 256>>>(out + (size_t)BT * VV);
    }
}